// round 2
// baseline (speedup 1.0000x reference)
#include <cuda_runtime.h>

#define B_ 8
#define T_ 12
#define N_ 1024
#define C_ 64
#define H_ 8
#define D_ 64
#define HD_ 512
#define BT_ 96
#define EPSV 1e-3f

// ---------------- scratch (device globals; no allocation) ----------------
__device__ float g_q[BT_ * HD_];
__device__ float g_k[BT_ * HD_];
__device__ float g_w[H_ * B_ * T_ * T_];
__device__ float g_agg[B_ * T_ * N_ * C_];          // 25 MB
__device__ float g_v[B_ * T_ * N_ * HD_];           // 201 MB (v, then update in-place)
__device__ double g_part[B_ * 96 * 2];
__device__ float g_stats[B_ * 4];

// ---------------- 1) q/k projections: [96,1024]@[1024,512] ----------------
__global__ void qk_kernel(const float* __restrict__ state,
                          const float* __restrict__ Wq, const float* __restrict__ bq,
                          const float* __restrict__ Wk, const float* __restrict__ bk) {
    __shared__ float s[N_];
    int bt = blockIdx.x;
    for (int i = threadIdx.x; i < N_; i += blockDim.x) s[i] = state[bt * N_ + i];
    __syncthreads();
    int hd = threadIdx.x;  // 512 threads
    float qa = 0.f, ka = 0.f;
#pragma unroll 4
    for (int m = 0; m < N_; m++) {
        float sv = s[m];
        qa = fmaf(sv, Wq[m * HD_ + hd], qa);
        ka = fmaf(sv, Wk[m * HD_ + hd], ka);
    }
    g_q[bt * HD_ + hd] = qa + bq[hd];
    g_k[bt * HD_ + hd] = ka + bk[hd];
}

// ---------------- 2) attention weights: 12x12 softmax per (h,b) ----------------
__global__ void attw_kernel() {
    __shared__ float sc[T_][T_];
    int b = blockIdx.x % B_;
    int h = blockIdx.x / B_;
    int t = threadIdx.x;
    int i = t / T_, j = t % T_;
    if (t < T_ * T_) {
        const float* qp = &g_q[(b * T_ + i) * HD_ + h * D_];
        const float* kp = &g_k[(b * T_ + j) * HD_ + h * D_];
        float d = 0.f;
#pragma unroll
        for (int x = 0; x < D_; x++) d = fmaf(qp[x], kp[x], d);
        sc[i][j] = d * 0.125f;
    }
    __syncthreads();
    if (t < T_ * T_) {
        float mx = -1e30f;
#pragma unroll
        for (int x = 0; x < T_; x++) mx = fmaxf(mx, sc[i][x]);
        float sm = 0.f;
#pragma unroll
        for (int x = 0; x < T_; x++) sm += expf(sc[i][x] - mx);
        g_w[((h * B_ + b) * T_ + i) * T_ + j] = expf(sc[i][j] - mx) / sm;
    }
}

// ---------------- 3) agg = adj @ signal as ONE GEMM: [1024,1024]@[1024,6144] ----
// Column j = bt*64 + c.  128x128 tile, 256 threads, 8x8 micro.
__global__ void __launch_bounds__(256, 2) agg2_kernel(const float* __restrict__ adj,
                                                      const float* __restrict__ sig) {
    __shared__ float As[16][132];
    __shared__ float Bs[16][132];
    int j0 = blockIdx.x * 128;
    int n0 = blockIdx.y * 128;
    int tid = threadIdx.x;
    int tx = tid & 15, ty = tid >> 4;
    float acc[8][8];
#pragma unroll
    for (int i = 0; i < 8; i++)
#pragma unroll
        for (int j = 0; j < 8; j++) acc[i][j] = 0.f;

    for (int k0 = 0; k0 < N_; k0 += 16) {
        // As[k][n] = adj[(n0+n)][k0+k]
        {
            int r = tid >> 1;
            int kb = (tid & 1) * 8;
            const float* src = adj + (size_t)(n0 + r) * N_ + k0 + kb;
            float4 v0 = *(const float4*)src;
            float4 v1 = *(const float4*)(src + 4);
            As[kb + 0][r] = v0.x; As[kb + 1][r] = v0.y;
            As[kb + 2][r] = v0.z; As[kb + 3][r] = v0.w;
            As[kb + 4][r] = v1.x; As[kb + 5][r] = v1.y;
            As[kb + 6][r] = v1.z; As[kb + 7][r] = v1.w;
        }
        // Bs[k][jf] = sig[bt][k0+k][c],  j = j0+jf
#pragma unroll
        for (int p = 0; p < 2; p++) {
            int f = tid + p * 256;
            int k = f >> 5;
            int jf = (f & 31) * 4;
            int j = j0 + jf;
            int bt = j >> 6, c = j & 63;
            *(float4*)&Bs[k][jf] =
                *(const float4*)(sig + (size_t)bt * (N_ * C_) + (k0 + k) * C_ + c);
        }
        __syncthreads();
#pragma unroll
        for (int kk = 0; kk < 16; kk++) {
            float4 a0 = *(const float4*)&As[kk][ty * 8];
            float4 a1 = *(const float4*)&As[kk][ty * 8 + 4];
            float4 b0 = *(const float4*)&Bs[kk][tx * 8];
            float4 b1 = *(const float4*)&Bs[kk][tx * 8 + 4];
            float a[8] = {a0.x, a0.y, a0.z, a0.w, a1.x, a1.y, a1.z, a1.w};
            float b[8] = {b0.x, b0.y, b0.z, b0.w, b1.x, b1.y, b1.z, b1.w};
#pragma unroll
            for (int i = 0; i < 8; i++)
#pragma unroll
                for (int j = 0; j < 8; j++) acc[i][j] = fmaf(a[i], b[j], acc[i][j]);
        }
        __syncthreads();
    }
    int j = j0 + tx * 8;
    int bt = j >> 6, c = j & 63;
    float* outb = g_agg + (size_t)bt * (N_ * C_) + c;
#pragma unroll
    for (int i = 0; i < 8; i++) {
        int n = n0 + ty * 8 + i;
        *(float4*)(outb + n * C_) = make_float4(acc[i][0], acc[i][1], acc[i][2], acc[i][3]);
        *(float4*)(outb + n * C_ + 4) = make_float4(acc[i][4], acc[i][5], acc[i][6], acc[i][7]);
    }
}

// ---------------- 4) v[bt] = agg[bt] @ Kg[t] + bg[t] : 128x128 tile ----------------
__global__ void __launch_bounds__(256, 2) v2_kernel(const float* __restrict__ Kg,
                                                    const float* __restrict__ bg) {
    __shared__ float As[16][132];
    __shared__ float Bs[16][132];
    int m0 = blockIdx.x * 128;
    int n0 = blockIdx.y * 128;
    int bt = blockIdx.z;
    int t = bt % T_;
    int tid = threadIdx.x;
    int tx = tid & 15, ty = tid >> 4;
    float acc[8][8];
#pragma unroll
    for (int i = 0; i < 8; i++)
#pragma unroll
        for (int j = 0; j < 8; j++) acc[i][j] = 0.f;

    const float* aggb = g_agg + (size_t)bt * (N_ * C_);
    const float* Kgt = Kg + (size_t)t * (C_ * HD_);

    for (int k0 = 0; k0 < C_; k0 += 16) {
        {
            int r = tid >> 1;
            int kb = (tid & 1) * 8;
            const float* src = aggb + (size_t)(n0 + r) * C_ + k0 + kb;
            float4 v0 = *(const float4*)src;
            float4 v1 = *(const float4*)(src + 4);
            As[kb + 0][r] = v0.x; As[kb + 1][r] = v0.y;
            As[kb + 2][r] = v0.z; As[kb + 3][r] = v0.w;
            As[kb + 4][r] = v1.x; As[kb + 5][r] = v1.y;
            As[kb + 6][r] = v1.z; As[kb + 7][r] = v1.w;
        }
#pragma unroll
        for (int p = 0; p < 2; p++) {
            int f = tid + p * 256;
            int k = f >> 5;
            int mf = (f & 31) * 4;
            *(float4*)&Bs[k][mf] =
                *(const float4*)(Kgt + (size_t)(k0 + k) * HD_ + m0 + mf);
        }
        __syncthreads();
#pragma unroll
        for (int kk = 0; kk < 16; kk++) {
            float4 a0 = *(const float4*)&As[kk][ty * 8];
            float4 a1 = *(const float4*)&As[kk][ty * 8 + 4];
            float4 b0 = *(const float4*)&Bs[kk][tx * 8];
            float4 b1 = *(const float4*)&Bs[kk][tx * 8 + 4];
            float a[8] = {a0.x, a0.y, a0.z, a0.w, a1.x, a1.y, a1.z, a1.w};
            float b[8] = {b0.x, b0.y, b0.z, b0.w, b1.x, b1.y, b1.z, b1.w};
#pragma unroll
            for (int i = 0; i < 8; i++)
#pragma unroll
                for (int j = 0; j < 8; j++) acc[i][j] = fmaf(a[i], b[j], acc[i][j]);
        }
        __syncthreads();
    }
    int m = m0 + tx * 8;
    float4 bg0 = *(const float4*)(bg + t * HD_ + m);
    float4 bg1 = *(const float4*)(bg + t * HD_ + m + 4);
    float* outb = g_v + (size_t)bt * (N_ * HD_) + m;
#pragma unroll
    for (int i = 0; i < 8; i++) {
        int n = n0 + ty * 8 + i;
        *(float4*)(outb + (size_t)n * HD_) =
            make_float4(acc[i][0] + bg0.x, acc[i][1] + bg0.y, acc[i][2] + bg0.z, acc[i][3] + bg0.w);
        *(float4*)(outb + (size_t)n * HD_ + 4) =
            make_float4(acc[i][4] + bg1.x, acc[i][5] + bg1.y, acc[i][6] + bg1.z, acc[i][7] + bg1.w);
    }
}

// 5) attention mix, IN-PLACE on g_v
__global__ void upd_kernel() {
    __shared__ float sw[H_ * T_ * T_];
    int b = blockIdx.z;
    int n = blockIdx.y;
    int m = blockIdx.x * 128 + threadIdx.x;
    for (int i = threadIdx.x; i < H_ * T_ * T_; i += 128) {
        int h = i / (T_ * T_);
        int r = i % (T_ * T_);
        sw[i] = g_w[(h * B_ + b) * (T_ * T_) + r];
    }
    __syncthreads();
    int h = m >> 6;
    size_t base = (size_t)(b * T_) * (N_ * HD_) + n * HD_ + m;
    float vv[T_];
#pragma unroll
    for (int k = 0; k < T_; k++) vv[k] = g_v[base + (size_t)k * (N_ * HD_)];
#pragma unroll
    for (int q = 0; q < T_; q++) {
        float a = 0.f;
#pragma unroll
        for (int k = 0; k < T_; k++) a = fmaf(sw[h * (T_ * T_) + q * T_ + k], vv[k], a);
        g_v[base + (size_t)q * (N_ * HD_)] = a;
    }
}

// 6) signal projection + ReLU + residual  (256x64 tile, 16x4 micro)
//    + state projection fused into the A-tile load path
__global__ void __launch_bounds__(256, 2) sigproj2_kernel(
    const float* __restrict__ Wf, const float* __restrict__ bf,
    const float* __restrict__ Ws, const float* __restrict__ bs,
    const float* __restrict__ sig, const float* __restrict__ state,
    float* __restrict__ out_sig, float* __restrict__ out_state) {
    __shared__ float As[16][260];
    __shared__ float Bs[16][68];
    __shared__ float sWs[HD_];
    int r0 = blockIdx.x * 256;
    int tid = threadIdx.x;
    int tx = tid & 15, ty = tid >> 4;  // tx: 4-col group, ty: 16-row group
    sWs[tid] = Ws[tid];
    sWs[tid + 256] = Ws[tid + 256];

    float acc[16][4];
#pragma unroll
    for (int i = 0; i < 16; i++)
#pragma unroll
        for (int j = 0; j < 4; j++) acc[i][j] = 0.f;
    float st = 0.f;
    __syncthreads();

    for (int k0 = 0; k0 < HD_; k0 += 16) {
        // As: one row per thread (row = r0+tid), 16 k values
        const float* src = g_v + (size_t)(r0 + tid) * HD_ + k0;
        float4 v0 = *(const float4*)src;
        float4 v1 = *(const float4*)(src + 4);
        float4 v2 = *(const float4*)(src + 8);
        float4 v3 = *(const float4*)(src + 12);
        As[0][tid] = v0.x;  As[1][tid] = v0.y;  As[2][tid] = v0.z;  As[3][tid] = v0.w;
        As[4][tid] = v1.x;  As[5][tid] = v1.y;  As[6][tid] = v1.z;  As[7][tid] = v1.w;
        As[8][tid] = v2.x;  As[9][tid] = v2.y;  As[10][tid] = v2.z; As[11][tid] = v2.w;
        As[12][tid] = v3.x; As[13][tid] = v3.y; As[14][tid] = v3.z; As[15][tid] = v3.w;
        // fused state dot-product (data already in registers)
        st = fmaf(v0.x, sWs[k0 + 0], st);  st = fmaf(v0.y, sWs[k0 + 1], st);
        st = fmaf(v0.z, sWs[k0 + 2], st);  st = fmaf(v0.w, sWs[k0 + 3], st);
        st = fmaf(v1.x, sWs[k0 + 4], st);  st = fmaf(v1.y, sWs[k0 + 5], st);
        st = fmaf(v1.z, sWs[k0 + 6], st);  st = fmaf(v1.w, sWs[k0 + 7], st);
        st = fmaf(v2.x, sWs[k0 + 8], st);  st = fmaf(v2.y, sWs[k0 + 9], st);
        st = fmaf(v2.z, sWs[k0 + 10], st); st = fmaf(v2.w, sWs[k0 + 11], st);
        st = fmaf(v3.x, sWs[k0 + 12], st); st = fmaf(v3.y, sWs[k0 + 13], st);
        st = fmaf(v3.z, sWs[k0 + 14], st); st = fmaf(v3.w, sWs[k0 + 15], st);
        // Bs[k][c] = Wf[(k0+k)*64 + c]
        *(float4*)&Bs[tid >> 4][(tid & 15) * 4] =
            *(const float4*)(Wf + (size_t)(k0 + (tid >> 4)) * C_ + (tid & 15) * 4);
        __syncthreads();
#pragma unroll
        for (int kk = 0; kk < 16; kk++) {
            float4 b = *(const float4*)&Bs[kk][tx * 4];
            float4 a0 = *(const float4*)&As[kk][ty * 16];
            float4 a1 = *(const float4*)&As[kk][ty * 16 + 4];
            float4 a2 = *(const float4*)&As[kk][ty * 16 + 8];
            float4 a3 = *(const float4*)&As[kk][ty * 16 + 12];
            float a[16] = {a0.x, a0.y, a0.z, a0.w, a1.x, a1.y, a1.z, a1.w,
                           a2.x, a2.y, a2.z, a2.w, a3.x, a3.y, a3.z, a3.w};
#pragma unroll
            for (int i = 0; i < 16; i++) {
                acc[i][0] = fmaf(a[i], b.x, acc[i][0]);
                acc[i][1] = fmaf(a[i], b.y, acc[i][1]);
                acc[i][2] = fmaf(a[i], b.z, acc[i][2]);
                acc[i][3] = fmaf(a[i], b.w, acc[i][3]);
            }
        }
        __syncthreads();
    }
    // state output (one row per thread)
    out_state[r0 + tid] = state[r0 + tid] + fmaxf(st + bs[0], 0.f);
    // signal output
    float4 bfv = *(const float4*)(bf + tx * 4);
#pragma unroll
    for (int i = 0; i < 16; i++) {
        int row = r0 + ty * 16 + i;
        const float4 sg = *(const float4*)(sig + (size_t)row * C_ + tx * 4);
        float4 o;
        o.x = fmaxf(acc[i][0] + bfv.x, 0.f) + sg.x;
        o.y = fmaxf(acc[i][1] + bfv.y, 0.f) + sg.y;
        o.z = fmaxf(acc[i][2] + bfv.z, 0.f) + sg.z;
        o.w = fmaxf(acc[i][3] + bfv.w, 0.f) + sg.w;
        *(float4*)(out_sig + (size_t)row * C_ + tx * 4) = o;
    }
}

// ---------------- 8-10) deterministic LayerNorm statistics ----------------
__global__ void red_state_kernel(const float* __restrict__ ys) {
    __shared__ double ss[256], sq[256];
    int b = blockIdx.x;
    int tid = threadIdx.x;
    double s = 0, q = 0;
    for (int i = tid; i < T_ * N_; i += 256) {
        double x = ys[b * T_ * N_ + i];
        s += x; q += x * x;
    }
    ss[tid] = s; sq[tid] = q;
    __syncthreads();
    for (int o = 128; o; o >>= 1) {
        if (tid < o) { ss[tid] += ss[tid + o]; sq[tid] += sq[tid + o]; }
        __syncthreads();
    }
    if (tid == 0) {
        double cnt = (double)(T_ * N_);
        double mean = ss[0] / cnt;
        double var = sq[0] / cnt - mean * mean;
        g_stats[b * 4 + 0] = (float)mean;
        g_stats[b * 4 + 1] = rsqrtf((float)var + EPSV);
    }
}

__global__ void red_sig1_kernel(const float* __restrict__ yg) {
    __shared__ double ss[256], sq[256];
    int b = blockIdx.y, blk = blockIdx.x;
    int tid = threadIdx.x;
    const float* base = yg + (size_t)b * (T_ * N_ * C_) + blk * 8192;
    double s = 0, q = 0;
    for (int i = tid; i < 8192; i += 256) {
        double x = base[i];
        s += x; q += x * x;
    }
    ss[tid] = s; sq[tid] = q;
    __syncthreads();
    for (int o = 128; o; o >>= 1) {
        if (tid < o) { ss[tid] += ss[tid + o]; sq[tid] += sq[tid + o]; }
        __syncthreads();
    }
    if (tid == 0) {
        g_part[(b * 96 + blk) * 2 + 0] = ss[0];
        g_part[(b * 96 + blk) * 2 + 1] = sq[0];
    }
}

__global__ void red_sig2_kernel() {
    __shared__ double ss[128], sq[128];
    int b = blockIdx.x;
    int tid = threadIdx.x;
    double s = 0, q = 0;
    if (tid < 96) {
        s = g_part[(b * 96 + tid) * 2 + 0];
        q = g_part[(b * 96 + tid) * 2 + 1];
    }
    ss[tid] = s; sq[tid] = q;
    __syncthreads();
    for (int o = 64; o; o >>= 1) {
        if (tid < o) { ss[tid] += ss[tid + o]; sq[tid] += sq[tid + o]; }
        __syncthreads();
    }
    if (tid == 0) {
        double cnt = (double)T_ * N_ * C_;
        double mean = ss[0] / cnt;
        double var = sq[0] / cnt - mean * mean;
        g_stats[b * 4 + 2] = (float)mean;
        g_stats[b * 4 + 3] = rsqrtf((float)var + EPSV);
    }
}

// ---------------- 11-12) in-place normalization ----------------
__global__ void norm_state_kernel(float* __restrict__ ys,
                                  const float* __restrict__ gamma,
                                  const float* __restrict__ beta) {
    int idx = blockIdx.x * 256 + threadIdx.x;
    int b = idx / (T_ * N_);
    int r = idx % (T_ * N_);
    float m = g_stats[b * 4 + 0];
    float rs = g_stats[b * 4 + 1];
    ys[idx] = (ys[idx] - m) * rs * gamma[r] + beta[r];
}

__global__ void norm_sig_kernel(float* __restrict__ yg,
                                const float* __restrict__ gamma,
                                const float* __restrict__ beta) {
    int idx = blockIdx.x * 256 + threadIdx.x;
    int b = idx / (T_ * N_ * C_);
    int r = idx % (T_ * N_ * C_);
    float m = g_stats[b * 4 + 2];
    float rs = g_stats[b * 4 + 3];
    yg[idx] = (yg[idx] - m) * rs * gamma[r] + beta[r];
}

// ---------------- launch ----------------
extern "C" void kernel_launch(void* const* d_in, const int* in_sizes, int n_in,
                              void* d_out, int out_size) {
    const float* graph_state  = (const float*)d_in[0];
    const float* graph_signal = (const float*)d_in[1];
    const float* adj          = (const float*)d_in[2];
    const float* Wq           = (const float*)d_in[3];
    const float* bq           = (const float*)d_in[4];
    const float* Wk           = (const float*)d_in[5];
    const float* bk           = (const float*)d_in[6];
    const float* Kg           = (const float*)d_in[7];
    const float* bg           = (const float*)d_in[8];
    const float* Ws           = (const float*)d_in[9];
    const float* bs           = (const float*)d_in[10];
    const float* Wf           = (const float*)d_in[11];
    const float* bf           = (const float*)d_in[12];
    const float* gs_gamma     = (const float*)d_in[13];
    const float* gs_beta      = (const float*)d_in[14];
    const float* sg_gamma     = (const float*)d_in[15];
    const float* sg_beta      = (const float*)d_in[16];

    float* out_state  = (float*)d_out;
    float* out_signal = out_state + BT_ * N_;

    qk_kernel<<<BT_, HD_>>>(graph_state, Wq, bq, Wk, bk);
    attw_kernel<<<H_ * B_, 160>>>();
    agg2_kernel<<<dim3(48, 8), 256>>>(adj, graph_signal);
    v2_kernel<<<dim3(HD_ / 128, N_ / 128, BT_), 256>>>(Kg, bg);
    upd_kernel<<<dim3(HD_ / 128, N_, B_), 128>>>();
    sigproj2_kernel<<<(BT_ * N_) / 256, 256>>>(Wf, bf, Ws, bs, graph_signal,
                                               graph_state, out_signal, out_state);
    red_state_kernel<<<B_, 256>>>(out_state);
    red_sig1_kernel<<<dim3(96, B_), 256>>>(out_signal);
    red_sig2_kernel<<<B_, 128>>>();
    norm_state_kernel<<<(BT_ * N_) / 256, 256>>>(out_state, gs_gamma, gs_beta);
    norm_sig_kernel<<<(BT_ * N_ * C_) / 256, 256>>>(out_signal, sg_gamma, sg_beta);
}

// round 3
// speedup vs baseline: 1.0553x; 1.0553x over previous
#include <cuda_runtime.h>

#define B_ 8
#define T_ 12
#define N_ 1024
#define C_ 64
#define H_ 8
#define D_ 64
#define HD_ 512
#define BT_ 96
#define EPSV 1e-3f

// ---------------- packed f32x2 helpers ----------------
__device__ __forceinline__ unsigned long long pack2(float lo, float hi) {
    unsigned long long r;
    asm("mov.b64 %0,{%1,%2};" : "=l"(r) : "f"(lo), "f"(hi));
    return r;
}
__device__ __forceinline__ void fma2(unsigned long long& d, unsigned long long a,
                                     unsigned long long b) {
    asm("fma.rn.f32x2 %0,%1,%2,%0;" : "+l"(d) : "l"(a), "l"(b));
}
__device__ __forceinline__ float2 unpack2(unsigned long long v) {
    float2 f;
    asm("mov.b64 {%0,%1},%2;" : "=f"(f.x), "=f"(f.y) : "l"(v));
    return f;
}

// ---------------- scratch (device globals; no allocation) ----------------
__device__ float g_q[BT_ * HD_];
__device__ float g_k[BT_ * HD_];
__device__ float g_w[H_ * B_ * T_ * T_];
__device__ float g_agg[B_ * T_ * N_ * C_];          // 25 MB
__device__ float g_v[B_ * T_ * N_ * HD_];           // 201 MB (v, then update in-place)
__device__ double g_part[B_ * 96 * 2];
__device__ float g_stats[B_ * 4];

// ---------------- 1) q/k projections ----------------
__global__ void qk_kernel(const float* __restrict__ state,
                          const float* __restrict__ Wq, const float* __restrict__ bq,
                          const float* __restrict__ Wk, const float* __restrict__ bk) {
    __shared__ float s[N_];
    int bt = blockIdx.x;
    for (int i = threadIdx.x; i < N_; i += blockDim.x) s[i] = state[bt * N_ + i];
    __syncthreads();
    int hd = threadIdx.x;
    float qa = 0.f, ka = 0.f;
#pragma unroll 4
    for (int m = 0; m < N_; m++) {
        float sv = s[m];
        qa = fmaf(sv, Wq[m * HD_ + hd], qa);
        ka = fmaf(sv, Wk[m * HD_ + hd], ka);
    }
    g_q[bt * HD_ + hd] = qa + bq[hd];
    g_k[bt * HD_ + hd] = ka + bk[hd];
}

// ---------------- 2) attention weights ----------------
__global__ void attw_kernel() {
    __shared__ float sc[T_][T_];
    int b = blockIdx.x % B_;
    int h = blockIdx.x / B_;
    int t = threadIdx.x;
    int i = t / T_, j = t % T_;
    if (t < T_ * T_) {
        const float* qp = &g_q[(b * T_ + i) * HD_ + h * D_];
        const float* kp = &g_k[(b * T_ + j) * HD_ + h * D_];
        float d = 0.f;
#pragma unroll
        for (int x = 0; x < D_; x++) d = fmaf(qp[x], kp[x], d);
        sc[i][j] = d * 0.125f;
    }
    __syncthreads();
    if (t < T_ * T_) {
        float mx = -1e30f;
#pragma unroll
        for (int x = 0; x < T_; x++) mx = fmaxf(mx, sc[i][x]);
        float sm = 0.f;
#pragma unroll
        for (int x = 0; x < T_; x++) sm += expf(sc[i][x] - mx);
        g_w[((h * B_ + b) * T_ + i) * T_ + j] = expf(sc[i][j] - mx) / sm;
    }
}

// ---------------- 3) agg = adj @ signal (one GEMM, f32x2 core) ----------------
__global__ void __launch_bounds__(256, 2) agg2_kernel(const float* __restrict__ adj,
                                                      const float* __restrict__ sig) {
    __shared__ float As[16][132];
    __shared__ float Bs[16][132];
    int j0 = blockIdx.x * 128;
    int n0 = blockIdx.y * 128;
    int tid = threadIdx.x;
    int tx = tid & 15, ty = tid >> 4;
    unsigned long long acc[8][4];
#pragma unroll
    for (int i = 0; i < 8; i++)
#pragma unroll
        for (int j = 0; j < 4; j++) acc[i][j] = 0ull;

    for (int k0 = 0; k0 < N_; k0 += 16) {
        {
            int r = tid >> 1;
            int kb = (tid & 1) * 8;
            const float* src = adj + (size_t)(n0 + r) * N_ + k0 + kb;
            float4 v0 = *(const float4*)src;
            float4 v1 = *(const float4*)(src + 4);
            As[kb + 0][r] = v0.x; As[kb + 1][r] = v0.y;
            As[kb + 2][r] = v0.z; As[kb + 3][r] = v0.w;
            As[kb + 4][r] = v1.x; As[kb + 5][r] = v1.y;
            As[kb + 6][r] = v1.z; As[kb + 7][r] = v1.w;
        }
#pragma unroll
        for (int p = 0; p < 2; p++) {
            int f = tid + p * 256;
            int k = f >> 5;
            int jf = (f & 31) * 4;
            int j = j0 + jf;
            int bt = j >> 6, c = j & 63;
            *(float4*)&Bs[k][jf] =
                *(const float4*)(sig + (size_t)bt * (N_ * C_) + (k0 + k) * C_ + c);
        }
        __syncthreads();
#pragma unroll
        for (int kk = 0; kk < 16; kk++) {
            float4 a0 = *(const float4*)&As[kk][ty * 8];
            float4 a1 = *(const float4*)&As[kk][ty * 8 + 4];
            ulonglong2 bp0 = *(const ulonglong2*)&Bs[kk][tx * 8];
            ulonglong2 bp1 = *(const ulonglong2*)&Bs[kk][tx * 8 + 4];
            unsigned long long ap[8];
            ap[0] = pack2(a0.x, a0.x); ap[1] = pack2(a0.y, a0.y);
            ap[2] = pack2(a0.z, a0.z); ap[3] = pack2(a0.w, a0.w);
            ap[4] = pack2(a1.x, a1.x); ap[5] = pack2(a1.y, a1.y);
            ap[6] = pack2(a1.z, a1.z); ap[7] = pack2(a1.w, a1.w);
#pragma unroll
            for (int i = 0; i < 8; i++) {
                fma2(acc[i][0], ap[i], bp0.x);
                fma2(acc[i][1], ap[i], bp0.y);
                fma2(acc[i][2], ap[i], bp1.x);
                fma2(acc[i][3], ap[i], bp1.y);
            }
        }
        __syncthreads();
    }
    int j = j0 + tx * 8;
    int bt = j >> 6, c = j & 63;
    float* outb = g_agg + (size_t)bt * (N_ * C_) + c;
#pragma unroll
    for (int i = 0; i < 8; i++) {
        int n = n0 + ty * 8 + i;
        float2 p0 = unpack2(acc[i][0]), p1 = unpack2(acc[i][1]);
        float2 p2 = unpack2(acc[i][2]), p3 = unpack2(acc[i][3]);
        *(float4*)(outb + n * C_) = make_float4(p0.x, p0.y, p1.x, p1.y);
        *(float4*)(outb + n * C_ + 4) = make_float4(p2.x, p2.y, p3.x, p3.y);
    }
}

// ---------------- 4) v[bt] = agg[bt] @ Kg[t] + bg[t]  (f32x2 core) ----------------
__global__ void __launch_bounds__(256, 2) v2_kernel(const float* __restrict__ Kg,
                                                    const float* __restrict__ bg) {
    __shared__ float As[16][132];
    __shared__ float Bs[16][132];
    int m0 = blockIdx.x * 128;
    int n0 = blockIdx.y * 128;
    int bt = blockIdx.z;
    int t = bt % T_;
    int tid = threadIdx.x;
    int tx = tid & 15, ty = tid >> 4;
    unsigned long long acc[8][4];
#pragma unroll
    for (int i = 0; i < 8; i++)
#pragma unroll
        for (int j = 0; j < 4; j++) acc[i][j] = 0ull;

    const float* aggb = g_agg + (size_t)bt * (N_ * C_);
    const float* Kgt = Kg + (size_t)t * (C_ * HD_);

    for (int k0 = 0; k0 < C_; k0 += 16) {
        {
            int r = tid >> 1;
            int kb = (tid & 1) * 8;
            const float* src = aggb + (size_t)(n0 + r) * C_ + k0 + kb;
            float4 v0 = *(const float4*)src;
            float4 v1 = *(const float4*)(src + 4);
            As[kb + 0][r] = v0.x; As[kb + 1][r] = v0.y;
            As[kb + 2][r] = v0.z; As[kb + 3][r] = v0.w;
            As[kb + 4][r] = v1.x; As[kb + 5][r] = v1.y;
            As[kb + 6][r] = v1.z; As[kb + 7][r] = v1.w;
        }
#pragma unroll
        for (int p = 0; p < 2; p++) {
            int f = tid + p * 256;
            int k = f >> 5;
            int mf = (f & 31) * 4;
            *(float4*)&Bs[k][mf] =
                *(const float4*)(Kgt + (size_t)(k0 + k) * HD_ + m0 + mf);
        }
        __syncthreads();
#pragma unroll
        for (int kk = 0; kk < 16; kk++) {
            float4 a0 = *(const float4*)&As[kk][ty * 8];
            float4 a1 = *(const float4*)&As[kk][ty * 8 + 4];
            ulonglong2 bp0 = *(const ulonglong2*)&Bs[kk][tx * 8];
            ulonglong2 bp1 = *(const ulonglong2*)&Bs[kk][tx * 8 + 4];
            unsigned long long ap[8];
            ap[0] = pack2(a0.x, a0.x); ap[1] = pack2(a0.y, a0.y);
            ap[2] = pack2(a0.z, a0.z); ap[3] = pack2(a0.w, a0.w);
            ap[4] = pack2(a1.x, a1.x); ap[5] = pack2(a1.y, a1.y);
            ap[6] = pack2(a1.z, a1.z); ap[7] = pack2(a1.w, a1.w);
#pragma unroll
            for (int i = 0; i < 8; i++) {
                fma2(acc[i][0], ap[i], bp0.x);
                fma2(acc[i][1], ap[i], bp0.y);
                fma2(acc[i][2], ap[i], bp1.x);
                fma2(acc[i][3], ap[i], bp1.y);
            }
        }
        __syncthreads();
    }
    int m = m0 + tx * 8;
    float4 bg0 = *(const float4*)(bg + t * HD_ + m);
    float4 bg1 = *(const float4*)(bg + t * HD_ + m + 4);
    float* outb = g_v + (size_t)bt * (N_ * HD_) + m;
#pragma unroll
    for (int i = 0; i < 8; i++) {
        int n = n0 + ty * 8 + i;
        float2 p0 = unpack2(acc[i][0]), p1 = unpack2(acc[i][1]);
        float2 p2 = unpack2(acc[i][2]), p3 = unpack2(acc[i][3]);
        *(float4*)(outb + (size_t)n * HD_) =
            make_float4(p0.x + bg0.x, p0.y + bg0.y, p1.x + bg0.z, p1.y + bg0.w);
        *(float4*)(outb + (size_t)n * HD_ + 4) =
            make_float4(p2.x + bg1.x, p2.y + bg1.y, p3.x + bg1.z, p3.y + bg1.w);
    }
}

// 5) attention mix, IN-PLACE on g_v
__global__ void upd_kernel() {
    __shared__ float sw[H_ * T_ * T_];
    int b = blockIdx.z;
    int n = blockIdx.y;
    int m = blockIdx.x * 128 + threadIdx.x;
    for (int i = threadIdx.x; i < H_ * T_ * T_; i += 128) {
        int h = i / (T_ * T_);
        int r = i % (T_ * T_);
        sw[i] = g_w[(h * B_ + b) * (T_ * T_) + r];
    }
    __syncthreads();
    int h = m >> 6;
    size_t base = (size_t)(b * T_) * (N_ * HD_) + n * HD_ + m;
    float vv[T_];
#pragma unroll
    for (int k = 0; k < T_; k++) vv[k] = g_v[base + (size_t)k * (N_ * HD_)];
#pragma unroll
    for (int q = 0; q < T_; q++) {
        float a = 0.f;
#pragma unroll
        for (int k = 0; k < T_; k++) a = fmaf(sw[h * (T_ * T_) + q * T_ + k], vv[k], a);
        g_v[base + (size_t)q * (N_ * HD_)] = a;
    }
}

// 6) signal projection + ReLU + residual (f32x2 core) + fused state projection
__global__ void __launch_bounds__(256, 2) sigproj2_kernel(
    const float* __restrict__ Wf, const float* __restrict__ bf,
    const float* __restrict__ Ws, const float* __restrict__ bs,
    const float* __restrict__ sig, const float* __restrict__ state,
    float* __restrict__ out_sig, float* __restrict__ out_state) {
    __shared__ float As[16][260];
    __shared__ float Bs[16][68];
    __shared__ float sWs[HD_];
    int r0 = blockIdx.x * 256;
    int tid = threadIdx.x;
    int tx = tid & 15, ty = tid >> 4;
    sWs[tid] = Ws[tid];
    sWs[tid + 256] = Ws[tid + 256];

    unsigned long long acc[16][2];
#pragma unroll
    for (int i = 0; i < 16; i++) { acc[i][0] = 0ull; acc[i][1] = 0ull; }
    float st = 0.f;
    __syncthreads();

    for (int k0 = 0; k0 < HD_; k0 += 16) {
        const float* src = g_v + (size_t)(r0 + tid) * HD_ + k0;
        float4 v0 = *(const float4*)src;
        float4 v1 = *(const float4*)(src + 4);
        float4 v2 = *(const float4*)(src + 8);
        float4 v3 = *(const float4*)(src + 12);
        As[0][tid] = v0.x;  As[1][tid] = v0.y;  As[2][tid] = v0.z;  As[3][tid] = v0.w;
        As[4][tid] = v1.x;  As[5][tid] = v1.y;  As[6][tid] = v1.z;  As[7][tid] = v1.w;
        As[8][tid] = v2.x;  As[9][tid] = v2.y;  As[10][tid] = v2.z; As[11][tid] = v2.w;
        As[12][tid] = v3.x; As[13][tid] = v3.y; As[14][tid] = v3.z; As[15][tid] = v3.w;
        st = fmaf(v0.x, sWs[k0 + 0], st);  st = fmaf(v0.y, sWs[k0 + 1], st);
        st = fmaf(v0.z, sWs[k0 + 2], st);  st = fmaf(v0.w, sWs[k0 + 3], st);
        st = fmaf(v1.x, sWs[k0 + 4], st);  st = fmaf(v1.y, sWs[k0 + 5], st);
        st = fmaf(v1.z, sWs[k0 + 6], st);  st = fmaf(v1.w, sWs[k0 + 7], st);
        st = fmaf(v2.x, sWs[k0 + 8], st);  st = fmaf(v2.y, sWs[k0 + 9], st);
        st = fmaf(v2.z, sWs[k0 + 10], st); st = fmaf(v2.w, sWs[k0 + 11], st);
        st = fmaf(v3.x, sWs[k0 + 12], st); st = fmaf(v3.y, sWs[k0 + 13], st);
        st = fmaf(v3.z, sWs[k0 + 14], st); st = fmaf(v3.w, sWs[k0 + 15], st);
        *(float4*)&Bs[tid >> 4][(tid & 15) * 4] =
            *(const float4*)(Wf + (size_t)(k0 + (tid >> 4)) * C_ + (tid & 15) * 4);
        __syncthreads();
#pragma unroll
        for (int kk = 0; kk < 16; kk++) {
            ulonglong2 bp = *(const ulonglong2*)&Bs[kk][tx * 4];
            float4 a0 = *(const float4*)&As[kk][ty * 16];
            float4 a1 = *(const float4*)&As[kk][ty * 16 + 4];
            float4 a2 = *(const float4*)&As[kk][ty * 16 + 8];
            float4 a3 = *(const float4*)&As[kk][ty * 16 + 12];
            unsigned long long ap[16];
            ap[0] = pack2(a0.x, a0.x);  ap[1] = pack2(a0.y, a0.y);
            ap[2] = pack2(a0.z, a0.z);  ap[3] = pack2(a0.w, a0.w);
            ap[4] = pack2(a1.x, a1.x);  ap[5] = pack2(a1.y, a1.y);
            ap[6] = pack2(a1.z, a1.z);  ap[7] = pack2(a1.w, a1.w);
            ap[8] = pack2(a2.x, a2.x);  ap[9] = pack2(a2.y, a2.y);
            ap[10] = pack2(a2.z, a2.z); ap[11] = pack2(a2.w, a2.w);
            ap[12] = pack2(a3.x, a3.x); ap[13] = pack2(a3.y, a3.y);
            ap[14] = pack2(a3.z, a3.z); ap[15] = pack2(a3.w, a3.w);
#pragma unroll
            for (int i = 0; i < 16; i++) {
                fma2(acc[i][0], ap[i], bp.x);
                fma2(acc[i][1], ap[i], bp.y);
            }
        }
        __syncthreads();
    }
    out_state[r0 + tid] = state[r0 + tid] + fmaxf(st + bs[0], 0.f);
    float4 bfv = *(const float4*)(bf + tx * 4);
#pragma unroll
    for (int i = 0; i < 16; i++) {
        int row = r0 + ty * 16 + i;
        const float4 sg = *(const float4*)(sig + (size_t)row * C_ + tx * 4);
        float2 p0 = unpack2(acc[i][0]);
        float2 p1 = unpack2(acc[i][1]);
        float4 o;
        o.x = fmaxf(p0.x + bfv.x, 0.f) + sg.x;
        o.y = fmaxf(p0.y + bfv.y, 0.f) + sg.y;
        o.z = fmaxf(p1.x + bfv.z, 0.f) + sg.z;
        o.w = fmaxf(p1.y + bfv.w, 0.f) + sg.w;
        *(float4*)(out_sig + (size_t)row * C_ + tx * 4) = o;
    }
}

// ---------------- 8-10) deterministic LayerNorm statistics ----------------
__global__ void red_state_kernel(const float* __restrict__ ys) {
    __shared__ double ss[256], sq[256];
    int b = blockIdx.x;
    int tid = threadIdx.x;
    double s = 0, q = 0;
    for (int i = tid; i < T_ * N_; i += 256) {
        double x = ys[b * T_ * N_ + i];
        s += x; q += x * x;
    }
    ss[tid] = s; sq[tid] = q;
    __syncthreads();
    for (int o = 128; o; o >>= 1) {
        if (tid < o) { ss[tid] += ss[tid + o]; sq[tid] += sq[tid + o]; }
        __syncthreads();
    }
    if (tid == 0) {
        double cnt = (double)(T_ * N_);
        double mean = ss[0] / cnt;
        double var = sq[0] / cnt - mean * mean;
        g_stats[b * 4 + 0] = (float)mean;
        g_stats[b * 4 + 1] = rsqrtf((float)var + EPSV);
    }
}

__global__ void red_sig1_kernel(const float* __restrict__ yg) {
    __shared__ double ss[256], sq[256];
    int b = blockIdx.y, blk = blockIdx.x;
    int tid = threadIdx.x;
    const float* base = yg + (size_t)b * (T_ * N_ * C_) + blk * 8192;
    double s = 0, q = 0;
    for (int i = tid; i < 8192; i += 256) {
        double x = base[i];
        s += x; q += x * x;
    }
    ss[tid] = s; sq[tid] = q;
    __syncthreads();
    for (int o = 128; o; o >>= 1) {
        if (tid < o) { ss[tid] += ss[tid + o]; sq[tid] += sq[tid + o]; }
        __syncthreads();
    }
    if (tid == 0) {
        g_part[(b * 96 + blk) * 2 + 0] = ss[0];
        g_part[(b * 96 + blk) * 2 + 1] = sq[0];
    }
}

__global__ void red_sig2_kernel() {
    __shared__ double ss[128], sq[128];
    int b = blockIdx.x;
    int tid = threadIdx.x;
    double s = 0, q = 0;
    if (tid < 96) {
        s = g_part[(b * 96 + tid) * 2 + 0];
        q = g_part[(b * 96 + tid) * 2 + 1];
    }
    ss[tid] = s; sq[tid] = q;
    __syncthreads();
    for (int o = 64; o; o >>= 1) {
        if (tid < o) { ss[tid] += ss[tid + o]; sq[tid] += sq[tid + o]; }
        __syncthreads();
    }
    if (tid == 0) {
        double cnt = (double)T_ * N_ * C_;
        double mean = ss[0] / cnt;
        double var = sq[0] / cnt - mean * mean;
        g_stats[b * 4 + 2] = (float)mean;
        g_stats[b * 4 + 3] = rsqrtf((float)var + EPSV);
    }
}

// ---------------- 11-12) in-place normalization ----------------
__global__ void norm_state_kernel(float* __restrict__ ys,
                                  const float* __restrict__ gamma,
                                  const float* __restrict__ beta) {
    int idx = blockIdx.x * 256 + threadIdx.x;
    int b = idx / (T_ * N_);
    int r = idx % (T_ * N_);
    float m = g_stats[b * 4 + 0];
    float rs = g_stats[b * 4 + 1];
    ys[idx] = (ys[idx] - m) * rs * gamma[r] + beta[r];
}

__global__ void norm_sig_kernel(float* __restrict__ yg,
                                const float* __restrict__ gamma,
                                const float* __restrict__ beta) {
    int idx = blockIdx.x * 256 + threadIdx.x;
    int b = idx / (T_ * N_ * C_);
    int r = idx % (T_ * N_ * C_);
    float m = g_stats[b * 4 + 2];
    float rs = g_stats[b * 4 + 3];
    yg[idx] = (yg[idx] - m) * rs * gamma[r] + beta[r];
}

// ---------------- launch ----------------
extern "C" void kernel_launch(void* const* d_in, const int* in_sizes, int n_in,
                              void* d_out, int out_size) {
    const float* graph_state  = (const float*)d_in[0];
    const float* graph_signal = (const float*)d_in[1];
    const float* adj          = (const float*)d_in[2];
    const float* Wq           = (const float*)d_in[3];
    const float* bq           = (const float*)d_in[4];
    const float* Wk           = (const float*)d_in[5];
    const float* bk           = (const float*)d_in[6];
    const float* Kg           = (const float*)d_in[7];
    const float* bg           = (const float*)d_in[8];
    const float* Ws           = (const float*)d_in[9];
    const float* bs           = (const float*)d_in[10];
    const float* Wf           = (const float*)d_in[11];
    const float* bf           = (const float*)d_in[12];
    const float* gs_gamma     = (const float*)d_in[13];
    const float* gs_beta      = (const float*)d_in[14];
    const float* sg_gamma     = (const float*)d_in[15];
    const float* sg_beta      = (const float*)d_in[16];

    float* out_state  = (float*)d_out;
    float* out_signal = out_state + BT_ * N_;

    qk_kernel<<<BT_, HD_>>>(graph_state, Wq, bq, Wk, bk);
    attw_kernel<<<H_ * B_, 160>>>();
    agg2_kernel<<<dim3(48, 8), 256>>>(adj, graph_signal);
    v2_kernel<<<dim3(HD_ / 128, N_ / 128, BT_), 256>>>(Kg, bg);
    upd_kernel<<<dim3(HD_ / 128, N_, B_), 128>>>();
    sigproj2_kernel<<<(BT_ * N_) / 256, 256>>>(Wf, bf, Ws, bs, graph_signal,
                                               graph_state, out_signal, out_state);
    red_state_kernel<<<B_, 256>>>(out_state);
    red_sig1_kernel<<<dim3(96, B_), 256>>>(out_signal);
    red_sig2_kernel<<<B_, 128>>>();
    norm_state_kernel<<<(BT_ * N_) / 256, 256>>>(out_state, gs_gamma, gs_beta);
    norm_sig_kernel<<<(BT_ * N_ * C_) / 256, 256>>>(out_signal, sg_gamma, sg_beta);
}

// round 5
// speedup vs baseline: 1.2789x; 1.2119x over previous
#include <cuda_runtime.h>
#include <cuda_bf16.h>

#define B_ 8
#define T_ 12
#define N_ 1024
#define C_ 64
#define H_ 8
#define D_ 64
#define HD_ 512
#define BT_ 96
#define EPSV 1e-3f

// ---------------- packed f32x2 helpers (for sigproj) ----------------
__device__ __forceinline__ unsigned long long pack2(float lo, float hi) {
    unsigned long long r;
    asm("mov.b64 %0,{%1,%2};" : "=l"(r) : "f"(lo), "f"(hi));
    return r;
}
__device__ __forceinline__ void fma2(unsigned long long& d, unsigned long long a,
                                     unsigned long long b) {
    asm("fma.rn.f32x2 %0,%1,%2,%0;" : "+l"(d) : "l"(a), "l"(b));
}
__device__ __forceinline__ float2 unpack2(unsigned long long v) {
    float2 f;
    asm("mov.b64 {%0,%1},%2;" : "=f"(f.x), "=f"(f.y) : "l"(v));
    return f;
}

// ---------------- bf16 split + mma helpers ----------------
// split x into hi+lo bf16s; pack two consecutive-k values into one u32.
__device__ __forceinline__ void split2(float x0, float x1, unsigned& hi, unsigned& lo) {
    __nv_bfloat16 h0 = __float2bfloat16(x0);
    __nv_bfloat16 h1 = __float2bfloat16(x1);
    __nv_bfloat16 l0 = __float2bfloat16(x0 - __bfloat162float(h0));
    __nv_bfloat16 l1 = __float2bfloat16(x1 - __bfloat162float(h1));
    hi = ((unsigned)__bfloat16_as_ushort(h1) << 16) | (unsigned)__bfloat16_as_ushort(h0);
    lo = ((unsigned)__bfloat16_as_ushort(l1) << 16) | (unsigned)__bfloat16_as_ushort(l0);
}

__device__ __forceinline__ void mma16816(float* c, unsigned a0, unsigned a1,
                                         unsigned a2, unsigned a3,
                                         unsigned b0, unsigned b1) {
    asm volatile(
        "mma.sync.aligned.m16n8k16.row.col.f32.bf16.bf16.f32 "
        "{%0,%1,%2,%3},{%4,%5,%6,%7},{%8,%9},{%0,%1,%2,%3};"
        : "+f"(c[0]), "+f"(c[1]), "+f"(c[2]), "+f"(c[3])
        : "r"(a0), "r"(a1), "r"(a2), "r"(a3), "r"(b0), "r"(b1));
}

// ---------------- scratch (device globals; no allocation) ----------------
__device__ float g_q[BT_ * HD_];
__device__ float g_k[BT_ * HD_];
__device__ float g_w[H_ * B_ * T_ * T_];
__device__ float g_agg[B_ * T_ * N_ * C_];          // 25 MB
__device__ float g_v[B_ * T_ * N_ * HD_];           // 201 MB (v, then update in-place)
__device__ double g_part[B_ * 96 * 2];
__device__ float g_stats[B_ * 4];

// ---------------- 1) q/k projections ----------------
__global__ void qk_kernel(const float* __restrict__ state,
                          const float* __restrict__ Wq, const float* __restrict__ bq,
                          const float* __restrict__ Wk, const float* __restrict__ bk) {
    __shared__ float s[N_];
    int bt = blockIdx.x;
    for (int i = threadIdx.x; i < N_; i += blockDim.x) s[i] = state[bt * N_ + i];
    __syncthreads();
    int hd = threadIdx.x;
    float qa = 0.f, ka = 0.f;
#pragma unroll 4
    for (int m = 0; m < N_; m++) {
        float sv = s[m];
        qa = fmaf(sv, Wq[m * HD_ + hd], qa);
        ka = fmaf(sv, Wk[m * HD_ + hd], ka);
    }
    g_q[bt * HD_ + hd] = qa + bq[hd];
    g_k[bt * HD_ + hd] = ka + bk[hd];
}

// ---------------- 2) attention weights ----------------
__global__ void attw_kernel() {
    __shared__ float sc[T_][T_];
    int b = blockIdx.x % B_;
    int h = blockIdx.x / B_;
    int t = threadIdx.x;
    int i = t / T_, j = t % T_;
    if (t < T_ * T_) {
        const float* qp = &g_q[(b * T_ + i) * HD_ + h * D_];
        const float* kp = &g_k[(b * T_ + j) * HD_ + h * D_];
        float d = 0.f;
#pragma unroll
        for (int x = 0; x < D_; x++) d = fmaf(qp[x], kp[x], d);
        sc[i][j] = d * 0.125f;
    }
    __syncthreads();
    if (t < T_ * T_) {
        float mx = -1e30f;
#pragma unroll
        for (int x = 0; x < T_; x++) mx = fmaxf(mx, sc[i][x]);
        float sm = 0.f;
#pragma unroll
        for (int x = 0; x < T_; x++) sm += expf(sc[i][x] - mx);
        g_w[((h * B_ + b) * T_ + i) * T_ + j] = expf(sc[i][j] - mx) / sm;
    }
}

// ---------------- 3) agg = adj @ sig_cat (tensor core, split bf16 3-mma) ----
// C[n, j] = sum_k adj[n,k]*sigcat[k,j],  j = bt*64+c, 6144 cols total.
// CTA: 128x128 tile, 8 warps, warp tile 64x32. KT=32 per iteration.
__global__ void __launch_bounds__(256) aggT_kernel(const float* __restrict__ adj,
                                                   const float* __restrict__ sig) {
    __shared__ unsigned Ah[16][136], Al[16][136], Bh[16][136], Bl[16][136];
    int j0 = blockIdx.x * 128;
    int n0 = blockIdx.y * 128;
    int tid = threadIdx.x, lane = tid & 31, wid = tid >> 5;
    int wm = (wid & 1) * 64, wn = (wid >> 1) * 32;
    int lq = lane >> 2, lr = lane & 3;

    float acc[4][4][4];
#pragma unroll
    for (int i = 0; i < 4; i++)
#pragma unroll
        for (int j = 0; j < 4; j++)
#pragma unroll
            for (int r = 0; r < 4; r++) acc[i][j][r] = 0.f;

    for (int k0 = 0; k0 < N_; k0 += 32) {
        // A tile: Ah/Al[kp][m] = split(adj[(n0+m)][k0+2kp..+1])
#pragma unroll
        for (int p = 0; p < 8; p++) {
            int e = tid + p * 256;          // 2048 slots
            int kp = e & 15, m = e >> 4;
            const float2 v = *(const float2*)(adj + (size_t)(n0 + m) * N_ + k0 + 2 * kp);
            unsigned h, l;
            split2(v.x, v.y, h, l);
            Ah[kp][m] = h; Al[kp][m] = l;
        }
        // B tile: Bh/Bl[kp][jf] = split(sig[bt][k0+2kp][c], sig[bt][k0+2kp+1][c])
#pragma unroll
        for (int p = 0; p < 8; p++) {
            int e = tid + p * 256;
            int kp = e >> 7, jf = e & 127;
            int j = j0 + jf, bt = j >> 6, c = j & 63;
            const float* s = sig + (size_t)bt * (N_ * C_) + (size_t)(k0 + 2 * kp) * C_ + c;
            unsigned h, l;
            split2(s[0], s[C_], h, l);
            Bh[kp][jf] = h; Bl[kp][jf] = l;
        }
        __syncthreads();
#pragma unroll
        for (int ks = 0; ks < 2; ks++) {
            int kb = ks * 8;
            unsigned bh[4][2], bl[4][2];
#pragma unroll
            for (int j = 0; j < 4; j++) {
                int col = wn + j * 8 + lq;
                bh[j][0] = Bh[kb + lr][col];     bh[j][1] = Bh[kb + lr + 4][col];
                bl[j][0] = Bl[kb + lr][col];     bl[j][1] = Bl[kb + lr + 4][col];
            }
#pragma unroll
            for (int i = 0; i < 4; i++) {
                int m = wm + i * 16 + lq;
                unsigned ah0 = Ah[kb + lr][m],     ah1 = Ah[kb + lr][m + 8];
                unsigned ah2 = Ah[kb + lr + 4][m], ah3 = Ah[kb + lr + 4][m + 8];
                unsigned al0 = Al[kb + lr][m],     al1 = Al[kb + lr][m + 8];
                unsigned al2 = Al[kb + lr + 4][m], al3 = Al[kb + lr + 4][m + 8];
#pragma unroll
                for (int j = 0; j < 4; j++) {
                    mma16816(acc[i][j], ah0, ah1, ah2, ah3, bh[j][0], bh[j][1]);
                    mma16816(acc[i][j], ah0, ah1, ah2, ah3, bl[j][0], bl[j][1]);
                    mma16816(acc[i][j], al0, al1, al2, al3, bh[j][0], bh[j][1]);
                }
            }
        }
        __syncthreads();
    }
    // epilogue: C[row, jcol] -> g_agg[bt][row][c]
#pragma unroll
    for (int i = 0; i < 4; i++) {
        int row = n0 + wm + i * 16 + lq;
#pragma unroll
        for (int j = 0; j < 4; j++) {
            int jcol = j0 + wn + j * 8 + lr * 2;
            int bt = jcol >> 6, c = jcol & 63;
            float* o = g_agg + (size_t)bt * (N_ * C_) + c;
            *(float2*)(o + (size_t)row * C_) = make_float2(acc[i][j][0], acc[i][j][1]);
            *(float2*)(o + (size_t)(row + 8) * C_) = make_float2(acc[i][j][2], acc[i][j][3]);
        }
    }
}

// ---------------- 4) v[bt] = agg[bt] @ Kg[t] + bg[t] (tensor core) ----------------
// M=n(1024 rows), N=m(512 cols), K=c(64).
__global__ void __launch_bounds__(256) vT_kernel(const float* __restrict__ Kg,
                                                 const float* __restrict__ bg) {
    __shared__ unsigned Ah[16][136], Al[16][136], Bh[16][136], Bl[16][136];
    int m0 = blockIdx.x * 128;
    int n0 = blockIdx.y * 128;
    int bt = blockIdx.z;
    int t = bt % T_;
    int tid = threadIdx.x, lane = tid & 31, wid = tid >> 5;
    int wm = (wid & 1) * 64, wn = (wid >> 1) * 32;
    int lq = lane >> 2, lr = lane & 3;

    const float* aggb = g_agg + (size_t)bt * (N_ * C_);
    const float* Kgt = Kg + (size_t)t * (C_ * HD_);

    float acc[4][4][4];
#pragma unroll
    for (int i = 0; i < 4; i++)
#pragma unroll
        for (int j = 0; j < 4; j++)
#pragma unroll
            for (int r = 0; r < 4; r++) acc[i][j][r] = 0.f;

    for (int k0 = 0; k0 < C_; k0 += 32) {
#pragma unroll
        for (int p = 0; p < 8; p++) {
            int e = tid + p * 256;
            int kp = e & 15, m = e >> 4;
            const float2 v = *(const float2*)(aggb + (size_t)(n0 + m) * C_ + k0 + 2 * kp);
            unsigned h, l;
            split2(v.x, v.y, h, l);
            Ah[kp][m] = h; Al[kp][m] = l;
        }
#pragma unroll
        for (int p = 0; p < 8; p++) {
            int e = tid + p * 256;
            int kp = e >> 7, jf = e & 127;
            const float* s = Kgt + (size_t)(k0 + 2 * kp) * HD_ + m0 + jf;
            unsigned h, l;
            split2(s[0], s[HD_], h, l);
            Bh[kp][jf] = h; Bl[kp][jf] = l;
        }
        __syncthreads();
#pragma unroll
        for (int ks = 0; ks < 2; ks++) {
            int kb = ks * 8;
            unsigned bh[4][2], bl[4][2];
#pragma unroll
            for (int j = 0; j < 4; j++) {
                int col = wn + j * 8 + lq;
                bh[j][0] = Bh[kb + lr][col];     bh[j][1] = Bh[kb + lr + 4][col];
                bl[j][0] = Bl[kb + lr][col];     bl[j][1] = Bl[kb + lr + 4][col];
            }
#pragma unroll
            for (int i = 0; i < 4; i++) {
                int m = wm + i * 16 + lq;
                unsigned ah0 = Ah[kb + lr][m],     ah1 = Ah[kb + lr][m + 8];
                unsigned ah2 = Ah[kb + lr + 4][m], ah3 = Ah[kb + lr + 4][m + 8];
                unsigned al0 = Al[kb + lr][m],     al1 = Al[kb + lr][m + 8];
                unsigned al2 = Al[kb + lr + 4][m], al3 = Al[kb + lr + 4][m + 8];
#pragma unroll
                for (int j = 0; j < 4; j++) {
                    mma16816(acc[i][j], ah0, ah1, ah2, ah3, bh[j][0], bh[j][1]);
                    mma16816(acc[i][j], ah0, ah1, ah2, ah3, bl[j][0], bl[j][1]);
                    mma16816(acc[i][j], al0, al1, al2, al3, bh[j][0], bh[j][1]);
                }
            }
        }
        __syncthreads();
    }
    float* outb = g_v + (size_t)bt * (N_ * HD_);
#pragma unroll
    for (int i = 0; i < 4; i++) {
        int row = n0 + wm + i * 16 + lq;
#pragma unroll
        for (int j = 0; j < 4; j++) {
            int col = m0 + wn + j * 8 + lr * 2;
            float2 bgv = *(const float2*)(bg + t * HD_ + col);
            *(float2*)(outb + (size_t)row * HD_ + col) =
                make_float2(acc[i][j][0] + bgv.x, acc[i][j][1] + bgv.y);
            *(float2*)(outb + (size_t)(row + 8) * HD_ + col) =
                make_float2(acc[i][j][2] + bgv.x, acc[i][j][3] + bgv.y);
        }
    }
}

// 5) attention mix, IN-PLACE on g_v
__global__ void upd_kernel() {
    __shared__ float sw[H_ * T_ * T_];
    int b = blockIdx.z;
    int n = blockIdx.y;
    int m = blockIdx.x * 128 + threadIdx.x;
    for (int i = threadIdx.x; i < H_ * T_ * T_; i += 128) {
        int h = i / (T_ * T_);
        int r = i % (T_ * T_);
        sw[i] = g_w[(h * B_ + b) * (T_ * T_) + r];
    }
    __syncthreads();
    int h = m >> 6;
    size_t base = (size_t)(b * T_) * (N_ * HD_) + n * HD_ + m;
    float vv[T_];
#pragma unroll
    for (int k = 0; k < T_; k++) vv[k] = g_v[base + (size_t)k * (N_ * HD_)];
#pragma unroll
    for (int q = 0; q < T_; q++) {
        float a = 0.f;
#pragma unroll
        for (int k = 0; k < T_; k++) a = fmaf(sw[h * (T_ * T_) + q * T_ + k], vv[k], a);
        g_v[base + (size_t)q * (N_ * HD_)] = a;
    }
}

// 6) signal projection + ReLU + residual (f32x2 core) + fused state projection
__global__ void __launch_bounds__(256, 2) sigproj2_kernel(
    const float* __restrict__ Wf, const float* __restrict__ bf,
    const float* __restrict__ Ws, const float* __restrict__ bs,
    const float* __restrict__ sig, const float* __restrict__ state,
    float* __restrict__ out_sig, float* __restrict__ out_state) {
    __shared__ float As[16][260];
    __shared__ float Bs[16][68];
    __shared__ float sWs[HD_];
    int r0 = blockIdx.x * 256;
    int tid = threadIdx.x;
    int tx = tid & 15, ty = tid >> 4;
    sWs[tid] = Ws[tid];
    sWs[tid + 256] = Ws[tid + 256];

    unsigned long long acc[16][2];
#pragma unroll
    for (int i = 0; i < 16; i++) { acc[i][0] = 0ull; acc[i][1] = 0ull; }
    float st = 0.f;
    __syncthreads();

    for (int k0 = 0; k0 < HD_; k0 += 16) {
        const float* src = g_v + (size_t)(r0 + tid) * HD_ + k0;
        float4 v0 = *(const float4*)src;
        float4 v1 = *(const float4*)(src + 4);
        float4 v2 = *(const float4*)(src + 8);
        float4 v3 = *(const float4*)(src + 12);
        As[0][tid] = v0.x;  As[1][tid] = v0.y;  As[2][tid] = v0.z;  As[3][tid] = v0.w;
        As[4][tid] = v1.x;  As[5][tid] = v1.y;  As[6][tid] = v1.z;  As[7][tid] = v1.w;
        As[8][tid] = v2.x;  As[9][tid] = v2.y;  As[10][tid] = v2.z; As[11][tid] = v2.w;
        As[12][tid] = v3.x; As[13][tid] = v3.y; As[14][tid] = v3.z; As[15][tid] = v3.w;
        st = fmaf(v0.x, sWs[k0 + 0], st);  st = fmaf(v0.y, sWs[k0 + 1], st);
        st = fmaf(v0.z, sWs[k0 + 2], st);  st = fmaf(v0.w, sWs[k0 + 3], st);
        st = fmaf(v1.x, sWs[k0 + 4], st);  st = fmaf(v1.y, sWs[k0 + 5], st);
        st = fmaf(v1.z, sWs[k0 + 6], st);  st = fmaf(v1.w, sWs[k0 + 7], st);
        st = fmaf(v2.x, sWs[k0 + 8], st);  st = fmaf(v2.y, sWs[k0 + 9], st);
        st = fmaf(v2.z, sWs[k0 + 10], st); st = fmaf(v2.w, sWs[k0 + 11], st);
        st = fmaf(v3.x, sWs[k0 + 12], st); st = fmaf(v3.y, sWs[k0 + 13], st);
        st = fmaf(v3.z, sWs[k0 + 14], st); st = fmaf(v3.w, sWs[k0 + 15], st);
        *(float4*)&Bs[tid >> 4][(tid & 15) * 4] =
            *(const float4*)(Wf + (size_t)(k0 + (tid >> 4)) * C_ + (tid & 15) * 4);
        __syncthreads();
#pragma unroll
        for (int kk = 0; kk < 16; kk++) {
            ulonglong2 bp = *(const ulonglong2*)&Bs[kk][tx * 4];
            float4 a0 = *(const float4*)&As[kk][ty * 16];
            float4 a1 = *(const float4*)&As[kk][ty * 16 + 4];
            float4 a2 = *(const float4*)&As[kk][ty * 16 + 8];
            float4 a3 = *(const float4*)&As[kk][ty * 16 + 12];
            unsigned long long ap[16];
            ap[0] = pack2(a0.x, a0.x);  ap[1] = pack2(a0.y, a0.y);
            ap[2] = pack2(a0.z, a0.z);  ap[3] = pack2(a0.w, a0.w);
            ap[4] = pack2(a1.x, a1.x);  ap[5] = pack2(a1.y, a1.y);
            ap[6] = pack2(a1.z, a1.z);  ap[7] = pack2(a1.w, a1.w);
            ap[8] = pack2(a2.x, a2.x);  ap[9] = pack2(a2.y, a2.y);
            ap[10] = pack2(a2.z, a2.z); ap[11] = pack2(a2.w, a2.w);
            ap[12] = pack2(a3.x, a3.x); ap[13] = pack2(a3.y, a3.y);
            ap[14] = pack2(a3.z, a3.z); ap[15] = pack2(a3.w, a3.w);
#pragma unroll
            for (int i = 0; i < 16; i++) {
                fma2(acc[i][0], ap[i], bp.x);
                fma2(acc[i][1], ap[i], bp.y);
            }
        }
        __syncthreads();
    }
    out_state[r0 + tid] = state[r0 + tid] + fmaxf(st + bs[0], 0.f);
    float4 bfv = *(const float4*)(bf + tx * 4);
#pragma unroll
    for (int i = 0; i < 16; i++) {
        int row = r0 + ty * 16 + i;
        const float4 sg = *(const float4*)(sig + (size_t)row * C_ + tx * 4);
        float2 p0 = unpack2(acc[i][0]);
        float2 p1 = unpack2(acc[i][1]);
        float4 o;
        o.x = fmaxf(p0.x + bfv.x, 0.f) + sg.x;
        o.y = fmaxf(p0.y + bfv.y, 0.f) + sg.y;
        o.z = fmaxf(p1.x + bfv.z, 0.f) + sg.z;
        o.w = fmaxf(p1.y + bfv.w, 0.f) + sg.w;
        *(float4*)(out_sig + (size_t)row * C_ + tx * 4) = o;
    }
}

// ---------------- 8-10) deterministic LayerNorm statistics ----------------
__global__ void red_state_kernel(const float* __restrict__ ys) {
    __shared__ double ss[256], sq[256];
    int b = blockIdx.x;
    int tid = threadIdx.x;
    double s = 0, q = 0;
    for (int i = tid; i < T_ * N_; i += 256) {
        double x = ys[b * T_ * N_ + i];
        s += x; q += x * x;
    }
    ss[tid] = s; sq[tid] = q;
    __syncthreads();
    for (int o = 128; o; o >>= 1) {
        if (tid < o) { ss[tid] += ss[tid + o]; sq[tid] += sq[tid + o]; }
        __syncthreads();
    }
    if (tid == 0) {
        double cnt = (double)(T_ * N_);
        double mean = ss[0] / cnt;
        double var = sq[0] / cnt - mean * mean;
        g_stats[b * 4 + 0] = (float)mean;
        g_stats[b * 4 + 1] = rsqrtf((float)var + EPSV);
    }
}

__global__ void red_sig1_kernel(const float* __restrict__ yg) {
    __shared__ double ss[256], sq[256];
    int b = blockIdx.y, blk = blockIdx.x;
    int tid = threadIdx.x;
    const float* base = yg + (size_t)b * (T_ * N_ * C_) + blk * 8192;
    double s = 0, q = 0;
    for (int i = tid; i < 8192; i += 256) {
        double x = base[i];
        s += x; q += x * x;
    }
    ss[tid] = s; sq[tid] = q;
    __syncthreads();
    for (int o = 128; o; o >>= 1) {
        if (tid < o) { ss[tid] += ss[tid + o]; sq[tid] += sq[tid + o]; }
        __syncthreads();
    }
    if (tid == 0) {
        g_part[(b * 96 + blk) * 2 + 0] = ss[0];
        g_part[(b * 96 + blk) * 2 + 1] = sq[0];
    }
}

__global__ void red_sig2_kernel() {
    __shared__ double ss[128], sq[128];
    int b = blockIdx.x;
    int tid = threadIdx.x;
    double s = 0, q = 0;
    if (tid < 96) {
        s = g_part[(b * 96 + tid) * 2 + 0];
        q = g_part[(b * 96 + tid) * 2 + 1];
    }
    ss[tid] = s; sq[tid] = q;
    __syncthreads();
    for (int o = 64; o; o >>= 1) {
        if (tid < o) { ss[tid] += ss[tid + o]; sq[tid] += sq[tid + o]; }
        __syncthreads();
    }
    if (tid == 0) {
        double cnt = (double)T_ * N_ * C_;
        double mean = ss[0] / cnt;
        double var = sq[0] / cnt - mean * mean;
        g_stats[b * 4 + 2] = (float)mean;
        g_stats[b * 4 + 3] = rsqrtf((float)var + EPSV);
    }
}

// ---------------- 11-12) in-place normalization ----------------
__global__ void norm_state_kernel(float* __restrict__ ys,
                                  const float* __restrict__ gamma,
                                  const float* __restrict__ beta) {
    int idx = blockIdx.x * 256 + threadIdx.x;
    int b = idx / (T_ * N_);
    int r = idx % (T_ * N_);
    float m = g_stats[b * 4 + 0];
    float rs = g_stats[b * 4 + 1];
    ys[idx] = (ys[idx] - m) * rs * gamma[r] + beta[r];
}

__global__ void norm_sig_kernel(float* __restrict__ yg,
                                const float* __restrict__ gamma,
                                const float* __restrict__ beta) {
    int idx = blockIdx.x * 256 + threadIdx.x;
    int b = idx / (T_ * N_ * C_);
    int r = idx % (T_ * N_ * C_);
    float m = g_stats[b * 4 + 2];
    float rs = g_stats[b * 4 + 3];
    yg[idx] = (yg[idx] - m) * rs * gamma[r] + beta[r];
}

// ---------------- launch ----------------
extern "C" void kernel_launch(void* const* d_in, const int* in_sizes, int n_in,
                              void* d_out, int out_size) {
    const float* graph_state  = (const float*)d_in[0];
    const float* graph_signal = (const float*)d_in[1];
    const float* adj          = (const float*)d_in[2];
    const float* Wq           = (const float*)d_in[3];
    const float* bq           = (const float*)d_in[4];
    const float* Wk           = (const float*)d_in[5];
    const float* bk           = (const float*)d_in[6];
    const float* Kg           = (const float*)d_in[7];
    const float* bg           = (const float*)d_in[8];
    const float* Ws           = (const float*)d_in[9];
    const float* bs           = (const float*)d_in[10];
    const float* Wf           = (const float*)d_in[11];
    const float* bf           = (const float*)d_in[12];
    const float* gs_gamma     = (const float*)d_in[13];
    const float* gs_beta      = (const float*)d_in[14];
    const float* sg_gamma     = (const float*)d_in[15];
    const float* sg_beta      = (const float*)d_in[16];

    float* out_state  = (float*)d_out;
    float* out_signal = out_state + BT_ * N_;

    qk_kernel<<<BT_, HD_>>>(graph_state, Wq, bq, Wk, bk);
    attw_kernel<<<H_ * B_, 160>>>();
    aggT_kernel<<<dim3(48, 8), 256>>>(adj, graph_signal);
    vT_kernel<<<dim3(HD_ / 128, N_ / 128, BT_), 256>>>(Kg, bg);
    upd_kernel<<<dim3(HD_ / 128, N_, B_), 128>>>();
    sigproj2_kernel<<<(BT_ * N_) / 256, 256>>>(Wf, bf, Ws, bs, graph_signal,
                                               graph_state, out_signal, out_state);
    red_state_kernel<<<B_, 256>>>(out_state);
    red_sig1_kernel<<<dim3(96, B_), 256>>>(out_signal);
    red_sig2_kernel<<<B_, 128>>>();
    norm_state_kernel<<<(BT_ * N_) / 256, 256>>>(out_state, gs_gamma, gs_beta);
    norm_sig_kernel<<<(BT_ * N_ * C_) / 256, 256>>>(out_signal, sg_gamma, sg_beta);
}

// round 6
// speedup vs baseline: 1.4066x; 1.0998x over previous
#include <cuda_runtime.h>
#include <cuda_bf16.h>

#define B_ 8
#define T_ 12
#define N_ 1024
#define C_ 64
#define H_ 8
#define D_ 64
#define HD_ 512
#define BT_ 96
#define EPSV 1e-3f

// ---------------- bf16 split + mma helpers ----------------
__device__ __forceinline__ void split2(float x0, float x1, unsigned& hi, unsigned& lo) {
    __nv_bfloat16 h0 = __float2bfloat16(x0);
    __nv_bfloat16 h1 = __float2bfloat16(x1);
    __nv_bfloat16 l0 = __float2bfloat16(x0 - __bfloat162float(h0));
    __nv_bfloat16 l1 = __float2bfloat16(x1 - __bfloat162float(h1));
    hi = ((unsigned)__bfloat16_as_ushort(h1) << 16) | (unsigned)__bfloat16_as_ushort(h0);
    lo = ((unsigned)__bfloat16_as_ushort(l1) << 16) | (unsigned)__bfloat16_as_ushort(l0);
}

__device__ __forceinline__ void mma16816(float* c, unsigned a0, unsigned a1,
                                         unsigned a2, unsigned a3,
                                         unsigned b0, unsigned b1) {
    asm volatile(
        "mma.sync.aligned.m16n8k16.row.col.f32.bf16.bf16.f32 "
        "{%0,%1,%2,%3},{%4,%5,%6,%7},{%8,%9},{%0,%1,%2,%3};"
        : "+f"(c[0]), "+f"(c[1]), "+f"(c[2]), "+f"(c[3])
        : "r"(a0), "r"(a1), "r"(a2), "r"(a3), "r"(b0), "r"(b1));
}

// ---------------- scratch ----------------
__device__ float g_q[BT_ * HD_];
__device__ float g_k[BT_ * HD_];
__device__ float g_w[H_ * B_ * T_ * T_];
__device__ float g_agg[B_ * T_ * N_ * C_];          // 25 MB
__device__ float g_v[B_ * T_ * N_ * HD_];           // 201 MB
__device__ float g_sv[BT_ * N_ * H_];               // 3 MB  per-head Ws dots
__device__ double g_part[B_ * 96 * 2];
__device__ float g_stats[B_ * 4];

// ---------------- 1) q/k projections ----------------
__global__ void qk_kernel(const float* __restrict__ state,
                          const float* __restrict__ Wq, const float* __restrict__ bq,
                          const float* __restrict__ Wk, const float* __restrict__ bk) {
    __shared__ float s[N_];
    int bt = blockIdx.x;
    for (int i = threadIdx.x; i < N_; i += blockDim.x) s[i] = state[bt * N_ + i];
    __syncthreads();
    int hd = threadIdx.x;
    float qa = 0.f, ka = 0.f;
#pragma unroll 4
    for (int m = 0; m < N_; m++) {
        float sv = s[m];
        qa = fmaf(sv, Wq[m * HD_ + hd], qa);
        ka = fmaf(sv, Wk[m * HD_ + hd], ka);
    }
    g_q[bt * HD_ + hd] = qa + bq[hd];
    g_k[bt * HD_ + hd] = ka + bk[hd];
}

// ---------------- 2) attention weights ----------------
__global__ void attw_kernel() {
    __shared__ float sc[T_][T_];
    int b = blockIdx.x % B_;
    int h = blockIdx.x / B_;
    int t = threadIdx.x;
    int i = t / T_, j = t % T_;
    if (t < T_ * T_) {
        const float* qp = &g_q[(b * T_ + i) * HD_ + h * D_];
        const float* kp = &g_k[(b * T_ + j) * HD_ + h * D_];
        float d = 0.f;
#pragma unroll
        for (int x = 0; x < D_; x++) d = fmaf(qp[x], kp[x], d);
        sc[i][j] = d * 0.125f;
    }
    __syncthreads();
    if (t < T_ * T_) {
        float mx = -1e30f;
#pragma unroll
        for (int x = 0; x < T_; x++) mx = fmaxf(mx, sc[i][x]);
        float sm = 0.f;
#pragma unroll
        for (int x = 0; x < T_; x++) sm += expf(sc[i][x] - mx);
        g_w[((h * B_ + b) * T_ + i) * T_ + j] = expf(sc[i][j] - mx) / sm;
    }
}

// ---------------- 3) agg = adj @ sig_cat (tensor, split bf16 3-mma) ----------------
__global__ void __launch_bounds__(256) aggT_kernel(const float* __restrict__ adj,
                                                   const float* __restrict__ sig) {
    __shared__ unsigned Ah[16][136], Al[16][136], Bh[16][136], Bl[16][136];
    int j0 = blockIdx.x * 128;
    int n0 = blockIdx.y * 128;
    int tid = threadIdx.x, lane = tid & 31, wid = tid >> 5;
    int wm = (wid & 1) * 64, wn = (wid >> 1) * 32;
    int lq = lane >> 2, lr = lane & 3;

    float acc[4][4][4];
#pragma unroll
    for (int i = 0; i < 4; i++)
#pragma unroll
        for (int j = 0; j < 4; j++)
#pragma unroll
            for (int r = 0; r < 4; r++) acc[i][j][r] = 0.f;

    for (int k0 = 0; k0 < N_; k0 += 32) {
#pragma unroll
        for (int p = 0; p < 8; p++) {
            int e = tid + p * 256;
            int kp = e & 15, m = e >> 4;
            const float2 v = *(const float2*)(adj + (size_t)(n0 + m) * N_ + k0 + 2 * kp);
            unsigned h, l;
            split2(v.x, v.y, h, l);
            Ah[kp][m] = h; Al[kp][m] = l;
        }
#pragma unroll
        for (int p = 0; p < 8; p++) {
            int e = tid + p * 256;
            int kp = e >> 7, jf = e & 127;
            int j = j0 + jf, bt = j >> 6, c = j & 63;
            const float* s = sig + (size_t)bt * (N_ * C_) + (size_t)(k0 + 2 * kp) * C_ + c;
            unsigned h, l;
            split2(s[0], s[C_], h, l);
            Bh[kp][jf] = h; Bl[kp][jf] = l;
        }
        __syncthreads();
#pragma unroll
        for (int ks = 0; ks < 2; ks++) {
            int kb = ks * 8;
            unsigned bh[4][2], bl[4][2];
#pragma unroll
            for (int j = 0; j < 4; j++) {
                int col = wn + j * 8 + lq;
                bh[j][0] = Bh[kb + lr][col];     bh[j][1] = Bh[kb + lr + 4][col];
                bl[j][0] = Bl[kb + lr][col];     bl[j][1] = Bl[kb + lr + 4][col];
            }
#pragma unroll
            for (int i = 0; i < 4; i++) {
                int m = wm + i * 16 + lq;
                unsigned ah0 = Ah[kb + lr][m],     ah1 = Ah[kb + lr][m + 8];
                unsigned ah2 = Ah[kb + lr + 4][m], ah3 = Ah[kb + lr + 4][m + 8];
                unsigned al0 = Al[kb + lr][m],     al1 = Al[kb + lr][m + 8];
                unsigned al2 = Al[kb + lr + 4][m], al3 = Al[kb + lr + 4][m + 8];
#pragma unroll
                for (int j = 0; j < 4; j++) {
                    mma16816(acc[i][j], ah0, ah1, ah2, ah3, bh[j][0], bh[j][1]);
                    mma16816(acc[i][j], ah0, ah1, ah2, ah3, bl[j][0], bl[j][1]);
                    mma16816(acc[i][j], al0, al1, al2, al3, bh[j][0], bh[j][1]);
                }
            }
        }
        __syncthreads();
    }
#pragma unroll
    for (int i = 0; i < 4; i++) {
        int row = n0 + wm + i * 16 + lq;
#pragma unroll
        for (int j = 0; j < 4; j++) {
            int jcol = j0 + wn + j * 8 + lr * 2;
            int bt = jcol >> 6, c = jcol & 63;
            float* o = g_agg + (size_t)bt * (N_ * C_) + c;
            *(float2*)(o + (size_t)row * C_) = make_float2(acc[i][j][0], acc[i][j][1]);
            *(float2*)(o + (size_t)(row + 8) * C_) = make_float2(acc[i][j][2], acc[i][j][3]);
        }
    }
}

// ---------------- 4) v = agg @ Kg + bg (tensor) + per-head Ws partial dots ----------
__global__ void __launch_bounds__(256) vT_kernel(const float* __restrict__ Kg,
                                                 const float* __restrict__ bg,
                                                 const float* __restrict__ Ws) {
    __shared__ unsigned Ah[16][136], Al[16][136], Bh[16][136], Bl[16][136];
    __shared__ float svp[128][2][2];
    int m0 = blockIdx.x * 128;
    int n0 = blockIdx.y * 128;
    int bt = blockIdx.z;
    int t = bt % T_;
    int tid = threadIdx.x, lane = tid & 31, wid = tid >> 5;
    int wm = (wid & 1) * 64, wn = (wid >> 1) * 32;
    int lq = lane >> 2, lr = lane & 3;

    const float* aggb = g_agg + (size_t)bt * (N_ * C_);
    const float* Kgt = Kg + (size_t)t * (C_ * HD_);

    float acc[4][4][4];
#pragma unroll
    for (int i = 0; i < 4; i++)
#pragma unroll
        for (int j = 0; j < 4; j++)
#pragma unroll
            for (int r = 0; r < 4; r++) acc[i][j][r] = 0.f;

    for (int k0 = 0; k0 < C_; k0 += 32) {
#pragma unroll
        for (int p = 0; p < 8; p++) {
            int e = tid + p * 256;
            int kp = e & 15, m = e >> 4;
            const float2 v = *(const float2*)(aggb + (size_t)(n0 + m) * C_ + k0 + 2 * kp);
            unsigned h, l;
            split2(v.x, v.y, h, l);
            Ah[kp][m] = h; Al[kp][m] = l;
        }
#pragma unroll
        for (int p = 0; p < 8; p++) {
            int e = tid + p * 256;
            int kp = e >> 7, jf = e & 127;
            const float* s = Kgt + (size_t)(k0 + 2 * kp) * HD_ + m0 + jf;
            unsigned h, l;
            split2(s[0], s[HD_], h, l);
            Bh[kp][jf] = h; Bl[kp][jf] = l;
        }
        __syncthreads();
#pragma unroll
        for (int ks = 0; ks < 2; ks++) {
            int kb = ks * 8;
            unsigned bh[4][2], bl[4][2];
#pragma unroll
            for (int j = 0; j < 4; j++) {
                int col = wn + j * 8 + lq;
                bh[j][0] = Bh[kb + lr][col];     bh[j][1] = Bh[kb + lr + 4][col];
                bl[j][0] = Bl[kb + lr][col];     bl[j][1] = Bl[kb + lr + 4][col];
            }
#pragma unroll
            for (int i = 0; i < 4; i++) {
                int m = wm + i * 16 + lq;
                unsigned ah0 = Ah[kb + lr][m],     ah1 = Ah[kb + lr][m + 8];
                unsigned ah2 = Ah[kb + lr + 4][m], ah3 = Ah[kb + lr + 4][m + 8];
                unsigned al0 = Al[kb + lr][m],     al1 = Al[kb + lr][m + 8];
                unsigned al2 = Al[kb + lr + 4][m], al3 = Al[kb + lr + 4][m + 8];
#pragma unroll
                for (int j = 0; j < 4; j++) {
                    mma16816(acc[i][j], ah0, ah1, ah2, ah3, bh[j][0], bh[j][1]);
                    mma16816(acc[i][j], ah0, ah1, ah2, ah3, bl[j][0], bl[j][1]);
                    mma16816(acc[i][j], al0, al1, al2, al3, bh[j][0], bh[j][1]);
                }
            }
        }
        __syncthreads();
    }
    // epilogue: store v (+bg) and reduce per-head Ws partial dots
    float* outb = g_v + (size_t)bt * (N_ * HD_);
    int hloc = wn >> 6;            // head-local index within this m-block (0/1)
    int band = (wn >> 5) & 1;      // which 32-col band of the head
#pragma unroll
    for (int i = 0; i < 4; i++) {
        int row = n0 + wm + i * 16 + lq;
        float p0 = 0.f, p1 = 0.f;
#pragma unroll
        for (int j = 0; j < 4; j++) {
            int col = m0 + wn + j * 8 + lr * 2;
            float2 bgv = *(const float2*)(bg + t * HD_ + col);
            float ws0 = Ws[col], ws1 = Ws[col + 1];
            float o00 = acc[i][j][0] + bgv.x, o01 = acc[i][j][1] + bgv.y;
            float o10 = acc[i][j][2] + bgv.x, o11 = acc[i][j][3] + bgv.y;
            *(float2*)(outb + (size_t)row * HD_ + col) = make_float2(o00, o01);
            *(float2*)(outb + (size_t)(row + 8) * HD_ + col) = make_float2(o10, o11);
            p0 = fmaf(o00, ws0, fmaf(o01, ws1, p0));
            p1 = fmaf(o10, ws0, fmaf(o11, ws1, p1));
        }
        p0 += __shfl_xor_sync(0xffffffffu, p0, 1);
        p0 += __shfl_xor_sync(0xffffffffu, p0, 2);
        p1 += __shfl_xor_sync(0xffffffffu, p1, 1);
        p1 += __shfl_xor_sync(0xffffffffu, p1, 2);
        if (lr == 0) {
            svp[wm + i * 16 + lq][hloc][band] = p0;
            svp[wm + i * 16 + lq + 8][hloc][band] = p1;
        }
    }
    __syncthreads();
    {
        int r = tid >> 1, hl = tid & 1;
        g_sv[((size_t)bt * N_ + n0 + r) * H_ + (m0 >> 6) + hl] =
            svp[r][hl][0] + svp[r][hl][1];
    }
}

// ---------------- 5) fused time-mix + signal projection (tensor) ----------------
// Block: (b, 16 nodes). Rows = 12 q x 16 n = 192, cols = 64 (Wf), K = 512.
// A tile built on the fly: A[q,n,k] = sum_t w[h(k),b,q,t] * v[b,t,n,k].
__global__ void __launch_bounds__(256) updsig_kernel(
    const float* __restrict__ Wf, const float* __restrict__ bf,
    const float* __restrict__ sig, float* __restrict__ out_sig) {
    __shared__ float Vt[12][16][20];            // v chunk [t][n][16k] (+pad)
    __shared__ unsigned Ah[8][200], Al[8][200]; // mixed+split A [kp][row 192]
    __shared__ unsigned Bh[8][72], Bl[8][72];   // Wf chunk split
    __shared__ float sws[H_][T_][T_];
    int n0 = blockIdx.x * 16;
    int b = blockIdx.y;
    int tid = threadIdx.x, lane = tid & 31, wid = tid >> 5;
    int wr = wid & 3, wc = wid >> 2;
    int lq = lane >> 2, lr = lane & 3;

    for (int i = tid; i < H_ * T_ * T_; i += 256)
        ((float*)sws)[i] = g_w[((i / 144) * B_ + b) * 144 + (i % 144)];

    float acc[3][4][4];
#pragma unroll
    for (int i = 0; i < 3; i++)
#pragma unroll
        for (int j = 0; j < 4; j++)
#pragma unroll
            for (int r = 0; r < 4; r++) acc[i][j][r] = 0.f;

    int qq = tid >> 4, ni = tid & 15;  // A-compute mapping (tid < 192)
    float wreg[T_];
    __syncthreads();

    for (int s = 0; s < 32; s++) {
        int k0 = s * 16;
        // phase 1: stage v[b, t, n0..n0+15, k0..k0+15]
#pragma unroll
        for (int p = 0; p < 3; p++) {
            int e = tid + p * 256;   // 768 float4 slots
            int r = e >> 2, f4 = e & 3;
            int t = r >> 4, nn = r & 15;
            float4 v = *(const float4*)(g_v +
                ((size_t)(b * T_ + t) * N_ + n0 + nn) * HD_ + k0 + f4 * 4);
            *(float4*)&Vt[t][nn][f4 * 4] = v;
        }
        __syncthreads();
        // phase 2: warps 0-5 mix+split A; warps 6-7 load Wf chunk
        if (tid < 192) {
            if ((s & 3) == 0) {
                int h = s >> 2;
#pragma unroll
                for (int t = 0; t < T_; t++) wreg[t] = sws[h][qq][t];
            }
            float s0[8], s1[8];
#pragma unroll
            for (int kp = 0; kp < 8; kp++) { s0[kp] = 0.f; s1[kp] = 0.f; }
#pragma unroll
            for (int t = 0; t < T_; t++) {
                float wv = wreg[t];
#pragma unroll
                for (int kp = 0; kp < 8; kp++) {
                    float2 v = *(const float2*)&Vt[t][ni][kp * 2];
                    s0[kp] = fmaf(wv, v.x, s0[kp]);
                    s1[kp] = fmaf(wv, v.y, s1[kp]);
                }
            }
#pragma unroll
            for (int kp = 0; kp < 8; kp++) {
                unsigned h, l;
                split2(s0[kp], s1[kp], h, l);
                Ah[kp][qq * 16 + ni] = h;
                Al[kp][qq * 16 + ni] = l;
            }
        } else {
            int t64 = tid - 192;
#pragma unroll
            for (int p = 0; p < 8; p++) {
                int e = t64 + p * 64;
                int kpp = e >> 6, c = e & 63;
                unsigned h, l;
                split2(Wf[(size_t)(k0 + 2 * kpp) * C_ + c],
                       Wf[(size_t)(k0 + 2 * kpp + 1) * C_ + c], h, l);
                Bh[kpp][c] = h; Bl[kpp][c] = l;
            }
        }
        __syncthreads();
        // phase 3: mma  (192x64, K=16)
        {
            unsigned bh[4][2], bl[4][2];
#pragma unroll
            for (int j = 0; j < 4; j++) {
                int col = wc * 32 + j * 8 + lq;
                bh[j][0] = Bh[lr][col];     bh[j][1] = Bh[lr + 4][col];
                bl[j][0] = Bl[lr][col];     bl[j][1] = Bl[lr + 4][col];
            }
#pragma unroll
            for (int i = 0; i < 3; i++) {
                int m = wr * 48 + i * 16 + lq;
                unsigned ah0 = Ah[lr][m],     ah1 = Ah[lr][m + 8];
                unsigned ah2 = Ah[lr + 4][m], ah3 = Ah[lr + 4][m + 8];
                unsigned al0 = Al[lr][m],     al1 = Al[lr][m + 8];
                unsigned al2 = Al[lr + 4][m], al3 = Al[lr + 4][m + 8];
#pragma unroll
                for (int j = 0; j < 4; j++) {
                    mma16816(acc[i][j], ah0, ah1, ah2, ah3, bh[j][0], bh[j][1]);
                    mma16816(acc[i][j], ah0, ah1, ah2, ah3, bl[j][0], bl[j][1]);
                    mma16816(acc[i][j], al0, al1, al2, al3, bh[j][0], bh[j][1]);
                }
            }
        }
        __syncthreads();
    }
    // epilogue: relu + bias + residual -> out_signal
#pragma unroll
    for (int i = 0; i < 3; i++) {
        int q_ = wr * 3 + i;
        int nn = n0 + lq;
#pragma unroll
        for (int j = 0; j < 4; j++) {
            int c = wc * 32 + j * 8 + lr * 2;
            float bf0 = bf[c], bf1 = bf[c + 1];
            size_t o0 = ((size_t)(b * T_ + q_) * N_ + nn) * C_ + c;
            size_t o1 = ((size_t)(b * T_ + q_) * N_ + nn + 8) * C_ + c;
            float2 sg0 = *(const float2*)(sig + o0);
            float2 sg1 = *(const float2*)(sig + o1);
            *(float2*)(out_sig + o0) =
                make_float2(fmaxf(acc[i][j][0] + bf0, 0.f) + sg0.x,
                            fmaxf(acc[i][j][1] + bf1, 0.f) + sg0.y);
            *(float2*)(out_sig + o1) =
                make_float2(fmaxf(acc[i][j][2] + bf0, 0.f) + sg1.x,
                            fmaxf(acc[i][j][3] + bf1, 0.f) + sg1.y);
        }
    }
}

// ---------------- 6) state mix: out_state from sv + w ----------------
__global__ void statemix_kernel(const float* __restrict__ state,
                                const float* __restrict__ bs,
                                float* __restrict__ out_state) {
    __shared__ float sws[H_][T_][T_];
    int b = blockIdx.y;
    int n = blockIdx.x * 128 + threadIdx.x;
    for (int i = threadIdx.x; i < H_ * T_ * T_; i += 128)
        ((float*)sws)[i] = g_w[((i / 144) * B_ + b) * 144 + (i % 144)];
    __syncthreads();
    float st[T_];
#pragma unroll
    for (int q = 0; q < T_; q++) st[q] = 0.f;
#pragma unroll
    for (int t = 0; t < T_; t++) {
        const float* svp = g_sv + ((size_t)(b * T_ + t) * N_ + n) * H_;
        float4 a = *(const float4*)svp;
        float4 c = *(const float4*)(svp + 4);
        float hv[8] = {a.x, a.y, a.z, a.w, c.x, c.y, c.z, c.w};
#pragma unroll
        for (int q = 0; q < T_; q++) {
            float s = 0.f;
#pragma unroll
            for (int h = 0; h < H_; h++) s = fmaf(sws[h][q][t], hv[h], s);
            st[q] += s;
        }
    }
#pragma unroll
    for (int q = 0; q < T_; q++) {
        size_t idx = (size_t)(b * T_ + q) * N_ + n;
        out_state[idx] = state[idx] + fmaxf(st[q] + bs[0], 0.f);
    }
}

// ---------------- LayerNorm statistics ----------------
__global__ void red_state_kernel(const float* __restrict__ ys) {
    __shared__ double ss[256], sq[256];
    int b = blockIdx.x;
    int tid = threadIdx.x;
    double s = 0, q = 0;
    for (int i = tid; i < T_ * N_; i += 256) {
        double x = ys[b * T_ * N_ + i];
        s += x; q += x * x;
    }
    ss[tid] = s; sq[tid] = q;
    __syncthreads();
    for (int o = 128; o; o >>= 1) {
        if (tid < o) { ss[tid] += ss[tid + o]; sq[tid] += sq[tid + o]; }
        __syncthreads();
    }
    if (tid == 0) {
        double cnt = (double)(T_ * N_);
        double mean = ss[0] / cnt;
        double var = sq[0] / cnt - mean * mean;
        g_stats[b * 4 + 0] = (float)mean;
        g_stats[b * 4 + 1] = rsqrtf((float)var + EPSV);
    }
}

__global__ void red_sig1_kernel(const float* __restrict__ yg) {
    __shared__ double ss[256], sq[256];
    int b = blockIdx.y, blk = blockIdx.x;
    int tid = threadIdx.x;
    const float* base = yg + (size_t)b * (T_ * N_ * C_) + blk * 8192;
    double s = 0, q = 0;
    for (int i = tid; i < 8192; i += 256) {
        double x = base[i];
        s += x; q += x * x;
    }
    ss[tid] = s; sq[tid] = q;
    __syncthreads();
    for (int o = 128; o; o >>= 1) {
        if (tid < o) { ss[tid] += ss[tid + o]; sq[tid] += sq[tid + o]; }
        __syncthreads();
    }
    if (tid == 0) {
        g_part[(b * 96 + blk) * 2 + 0] = ss[0];
        g_part[(b * 96 + blk) * 2 + 1] = sq[0];
    }
}

__global__ void red_sig2_kernel() {
    __shared__ double ss[128], sq[128];
    int b = blockIdx.x;
    int tid = threadIdx.x;
    double s = 0, q = 0;
    if (tid < 96) {
        s = g_part[(b * 96 + tid) * 2 + 0];
        q = g_part[(b * 96 + tid) * 2 + 1];
    }
    ss[tid] = s; sq[tid] = q;
    __syncthreads();
    for (int o = 64; o; o >>= 1) {
        if (tid < o) { ss[tid] += ss[tid + o]; sq[tid] += sq[tid + o]; }
        __syncthreads();
    }
    if (tid == 0) {
        double cnt = (double)T_ * N_ * C_;
        double mean = ss[0] / cnt;
        double var = sq[0] / cnt - mean * mean;
        g_stats[b * 4 + 2] = (float)mean;
        g_stats[b * 4 + 3] = rsqrtf((float)var + EPSV);
    }
}

// ---------------- in-place normalization ----------------
__global__ void norm_state_kernel(float* __restrict__ ys,
                                  const float* __restrict__ gamma,
                                  const float* __restrict__ beta) {
    int idx = blockIdx.x * 256 + threadIdx.x;
    int b = idx / (T_ * N_);
    int r = idx % (T_ * N_);
    float m = g_stats[b * 4 + 0];
    float rs = g_stats[b * 4 + 1];
    ys[idx] = (ys[idx] - m) * rs * gamma[r] + beta[r];
}

__global__ void norm_sig_kernel(float* __restrict__ yg,
                                const float* __restrict__ gamma,
                                const float* __restrict__ beta) {
    int idx = blockIdx.x * 256 + threadIdx.x;
    int b = idx / (T_ * N_ * C_);
    int r = idx % (T_ * N_ * C_);
    float m = g_stats[b * 4 + 2];
    float rs = g_stats[b * 4 + 3];
    yg[idx] = (yg[idx] - m) * rs * gamma[r] + beta[r];
}

// ---------------- launch ----------------
extern "C" void kernel_launch(void* const* d_in, const int* in_sizes, int n_in,
                              void* d_out, int out_size) {
    const float* graph_state  = (const float*)d_in[0];
    const float* graph_signal = (const float*)d_in[1];
    const float* adj          = (const float*)d_in[2];
    const float* Wq           = (const float*)d_in[3];
    const float* bq           = (const float*)d_in[4];
    const float* Wk           = (const float*)d_in[5];
    const float* bk           = (const float*)d_in[6];
    const float* Kg           = (const float*)d_in[7];
    const float* bg           = (const float*)d_in[8];
    const float* Ws           = (const float*)d_in[9];
    const float* bs           = (const float*)d_in[10];
    const float* Wf           = (const float*)d_in[11];
    const float* bf           = (const float*)d_in[12];
    const float* gs_gamma     = (const float*)d_in[13];
    const float* gs_beta      = (const float*)d_in[14];
    const float* sg_gamma     = (const float*)d_in[15];
    const float* sg_beta      = (const float*)d_in[16];

    float* out_state  = (float*)d_out;
    float* out_signal = out_state + BT_ * N_;

    qk_kernel<<<BT_, HD_>>>(graph_state, Wq, bq, Wk, bk);
    attw_kernel<<<H_ * B_, 160>>>();
    aggT_kernel<<<dim3(48, 8), 256>>>(adj, graph_signal);
    vT_kernel<<<dim3(HD_ / 128, N_ / 128, BT_), 256>>>(Kg, bg, Ws);
    updsig_kernel<<<dim3(64, 8), 256>>>(Wf, bf, graph_signal, out_signal);
    statemix_kernel<<<dim3(8, 8), 128>>>(graph_state, bs, out_state);
    red_state_kernel<<<B_, 256>>>(out_state);
    red_sig1_kernel<<<dim3(96, B_), 256>>>(out_signal);
    red_sig2_kernel<<<B_, 128>>>();
    norm_state_kernel<<<(BT_ * N_) / 256, 256>>>(out_state, gs_gamma, gs_beta);
    norm_sig_kernel<<<(BT_ * N_ * C_) / 256, 256>>>(out_signal, sg_gamma, sg_beta);
}

// round 7
// speedup vs baseline: 1.5220x; 1.0820x over previous
#include <cuda_runtime.h>
#include <cuda_bf16.h>

#define B_ 8
#define T_ 12
#define N_ 1024
#define C_ 64
#define H_ 8
#define D_ 64
#define HD_ 512
#define BT_ 96
#define EPSV 1e-3f

// ---------------- bf16 split + mma helpers ----------------
__device__ __forceinline__ void split2(float x0, float x1, unsigned& hi, unsigned& lo) {
    __nv_bfloat16 h0 = __float2bfloat16(x0);
    __nv_bfloat16 h1 = __float2bfloat16(x1);
    __nv_bfloat16 l0 = __float2bfloat16(x0 - __bfloat162float(h0));
    __nv_bfloat16 l1 = __float2bfloat16(x1 - __bfloat162float(h1));
    hi = ((unsigned)__bfloat16_as_ushort(h1) << 16) | (unsigned)__bfloat16_as_ushort(h0);
    lo = ((unsigned)__bfloat16_as_ushort(l1) << 16) | (unsigned)__bfloat16_as_ushort(l0);
}
__device__ __forceinline__ unsigned long long splitpack(float x0, float x1) {
    unsigned h, l;
    split2(x0, x1, h, l);
    return (unsigned long long)h | ((unsigned long long)l << 32);
}

__device__ __forceinline__ void mma16816(float* c, unsigned a0, unsigned a1,
                                         unsigned a2, unsigned a3,
                                         unsigned b0, unsigned b1) {
    asm volatile(
        "mma.sync.aligned.m16n8k16.row.col.f32.bf16.bf16.f32 "
        "{%0,%1,%2,%3},{%4,%5,%6,%7},{%8,%9},{%0,%1,%2,%3};"
        : "+f"(c[0]), "+f"(c[1]), "+f"(c[2]), "+f"(c[3])
        : "r"(a0), "r"(a1), "r"(a2), "r"(a3), "r"(b0), "r"(b1));
}

// ---------------- scratch ----------------
__device__ float g_q[BT_ * HD_];
__device__ float g_k[BT_ * HD_];
__device__ float g_w[H_ * B_ * T_ * T_];
__device__ unsigned long long g_adjs[N_ * (N_ / 2)];            // 4 MB  split adj
__device__ unsigned long long g_sigs[BT_ * (N_ / 2) * C_];      // 25 MB split signal
__device__ unsigned long long g_kgs[T_ * (C_ / 2) * HD_];       // 1.5 MB split Kg
__device__ unsigned long long g_aggs[(size_t)BT_ * N_ * (C_ / 2)]; // 25 MB split agg
__device__ float g_v[(size_t)B_ * T_ * N_ * HD_];               // 201 MB
__device__ float g_sv[BT_ * N_ * H_];                           // 3 MB
__device__ double g_part[B_ * 96 * 2];
__device__ float g_stats[B_ * 4];

// ---------------- 0) pre-split kernels ----------------
__global__ void presplit_adj_kernel(const float* __restrict__ adj) {
    int idx = blockIdx.x * 256 + threadIdx.x;           // N*N/2 = 524288
    int n = idx >> 9, kp = idx & 511;
    float2 v = *(const float2*)(adj + (size_t)n * N_ + 2 * kp);
    g_adjs[idx] = splitpack(v.x, v.y);
}
__global__ void presplit_sig_kernel(const float* __restrict__ sig) {
    int idx = blockIdx.x * 256 + threadIdx.x;           // BT*(N/2)*C = 3145728
    int bt = idx / ((N_ / 2) * C_);
    int r = idx % ((N_ / 2) * C_);
    int kp = r / C_, c = r % C_;
    const float* s = sig + ((size_t)bt * N_ + 2 * kp) * C_ + c;
    g_sigs[idx] = splitpack(s[0], s[C_]);
}
__global__ void presplit_kg_kernel(const float* __restrict__ Kg) {
    int idx = blockIdx.x * 256 + threadIdx.x;           // T*(C/2)*HD = 196608
    int t = idx / ((C_ / 2) * HD_);
    int r = idx % ((C_ / 2) * HD_);
    int kp = r / HD_, m = r % HD_;
    const float* s = Kg + ((size_t)t * C_ + 2 * kp) * HD_ + m;
    g_kgs[idx] = splitpack(s[0], s[HD_]);
}

// ---------------- 1) q/k projections ----------------
__global__ void qk_kernel(const float* __restrict__ state,
                          const float* __restrict__ Wq, const float* __restrict__ bq,
                          const float* __restrict__ Wk, const float* __restrict__ bk) {
    __shared__ float s[N_];
    int bt = blockIdx.x;
    for (int i = threadIdx.x; i < N_; i += blockDim.x) s[i] = state[bt * N_ + i];
    __syncthreads();
    int hd = threadIdx.x;
    float qa = 0.f, ka = 0.f;
#pragma unroll 4
    for (int m = 0; m < N_; m++) {
        float sv = s[m];
        qa = fmaf(sv, Wq[m * HD_ + hd], qa);
        ka = fmaf(sv, Wk[m * HD_ + hd], ka);
    }
    g_q[bt * HD_ + hd] = qa + bq[hd];
    g_k[bt * HD_ + hd] = ka + bk[hd];
}

// ---------------- 2) attention weights ----------------
__global__ void attw_kernel() {
    __shared__ float sc[T_][T_];
    int b = blockIdx.x % B_;
    int h = blockIdx.x / B_;
    int t = threadIdx.x;
    int i = t / T_, j = t % T_;
    if (t < T_ * T_) {
        const float* qp = &g_q[(b * T_ + i) * HD_ + h * D_];
        const float* kp = &g_k[(b * T_ + j) * HD_ + h * D_];
        float d = 0.f;
#pragma unroll
        for (int x = 0; x < D_; x++) d = fmaf(qp[x], kp[x], d);
        sc[i][j] = d * 0.125f;
    }
    __syncthreads();
    if (t < T_ * T_) {
        float mx = -1e30f;
#pragma unroll
        for (int x = 0; x < T_; x++) mx = fmaxf(mx, sc[i][x]);
        float sm = 0.f;
#pragma unroll
        for (int x = 0; x < T_; x++) sm += expf(sc[i][x] - mx);
        g_w[((h * B_ + b) * T_ + i) * T_ + j] = expf(sc[i][j] - mx) / sm;
    }
}

// ---------------- 3) agg = adj @ sig_cat (tensor, pre-split inputs) ----------------
__global__ void __launch_bounds__(256, 2) aggT_kernel() {
    __shared__ unsigned Ah[16][136], Al[16][136], Bh[16][136], Bl[16][136];
    int j0 = blockIdx.x * 128;
    int n0 = blockIdx.y * 128;
    int tid = threadIdx.x, lane = tid & 31, wid = tid >> 5;
    int wm = (wid & 1) * 64, wn = (wid >> 1) * 32;
    int lq = lane >> 2, lr = lane & 3;

    float acc[4][4][4];
#pragma unroll
    for (int i = 0; i < 4; i++)
#pragma unroll
        for (int j = 0; j < 4; j++)
#pragma unroll
            for (int r = 0; r < 4; r++) acc[i][j][r] = 0.f;

    for (int k0 = 0; k0 < N_; k0 += 32) {
        int kp0 = k0 >> 1;
#pragma unroll
        for (int p = 0; p < 8; p++) {
            int e = tid + p * 256;
            int kp = e & 15, m = e >> 4;
            unsigned long long v = g_adjs[(size_t)(n0 + m) * (N_ / 2) + kp0 + kp];
            Ah[kp][m] = (unsigned)v; Al[kp][m] = (unsigned)(v >> 32);
        }
#pragma unroll
        for (int p = 0; p < 8; p++) {
            int e = tid + p * 256;
            int kp = e >> 7, jf = e & 127;
            int j = j0 + jf, bt = j >> 6, c = j & 63;
            unsigned long long v =
                g_sigs[((size_t)bt * (N_ / 2) + kp0 + kp) * C_ + c];
            Bh[kp][jf] = (unsigned)v; Bl[kp][jf] = (unsigned)(v >> 32);
        }
        __syncthreads();
#pragma unroll
        for (int ks = 0; ks < 2; ks++) {
            int kb = ks * 8;
            unsigned bh[4][2], bl[4][2];
#pragma unroll
            for (int j = 0; j < 4; j++) {
                int col = wn + j * 8 + lq;
                bh[j][0] = Bh[kb + lr][col];     bh[j][1] = Bh[kb + lr + 4][col];
                bl[j][0] = Bl[kb + lr][col];     bl[j][1] = Bl[kb + lr + 4][col];
            }
#pragma unroll
            for (int i = 0; i < 4; i++) {
                int m = wm + i * 16 + lq;
                unsigned ah0 = Ah[kb + lr][m],     ah1 = Ah[kb + lr][m + 8];
                unsigned ah2 = Ah[kb + lr + 4][m], ah3 = Ah[kb + lr + 4][m + 8];
                unsigned al0 = Al[kb + lr][m],     al1 = Al[kb + lr][m + 8];
                unsigned al2 = Al[kb + lr + 4][m], al3 = Al[kb + lr + 4][m + 8];
#pragma unroll
                for (int j = 0; j < 4; j++) {
                    mma16816(acc[i][j], ah0, ah1, ah2, ah3, bh[j][0], bh[j][1]);
                    mma16816(acc[i][j], ah0, ah1, ah2, ah3, bl[j][0], bl[j][1]);
                    mma16816(acc[i][j], al0, al1, al2, al3, bh[j][0], bh[j][1]);
                }
            }
        }
        __syncthreads();
    }
    // epilogue: write agg in SPLIT form (u64 per c-pair)
#pragma unroll
    for (int i = 0; i < 4; i++) {
        int row = n0 + wm + i * 16 + lq;
#pragma unroll
        for (int j = 0; j < 4; j++) {
            int jcol = j0 + wn + j * 8 + lr * 2;
            int bt = jcol >> 6, c2 = (jcol & 63) >> 1;
            unsigned long long* o = g_aggs + ((size_t)bt * N_) * (C_ / 2) + c2;
            o[(size_t)row * (C_ / 2)] = splitpack(acc[i][j][0], acc[i][j][1]);
            o[(size_t)(row + 8) * (C_ / 2)] = splitpack(acc[i][j][2], acc[i][j][3]);
        }
    }
}

// ---------------- 4) v = agg @ Kg + bg (tensor, pre-split) + Ws partial dots ------
__global__ void __launch_bounds__(256, 2) vT_kernel(const float* __restrict__ bg,
                                                    const float* __restrict__ Ws) {
    __shared__ unsigned Ah[16][136], Al[16][136], Bh[16][136], Bl[16][136];
    __shared__ float svp[128][2][2];
    int m0 = blockIdx.x * 128;
    int n0 = blockIdx.y * 128;
    int bt = blockIdx.z;
    int t = bt % T_;
    int tid = threadIdx.x, lane = tid & 31, wid = tid >> 5;
    int wm = (wid & 1) * 64, wn = (wid >> 1) * 32;
    int lq = lane >> 2, lr = lane & 3;

    float acc[4][4][4];
#pragma unroll
    for (int i = 0; i < 4; i++)
#pragma unroll
        for (int j = 0; j < 4; j++)
#pragma unroll
            for (int r = 0; r < 4; r++) acc[i][j][r] = 0.f;

    for (int k0 = 0; k0 < C_; k0 += 32) {
        int kp0 = k0 >> 1;
#pragma unroll
        for (int p = 0; p < 8; p++) {
            int e = tid + p * 256;
            int kp = e & 15, m = e >> 4;
            unsigned long long v =
                g_aggs[((size_t)bt * N_ + n0 + m) * (C_ / 2) + kp0 + kp];
            Ah[kp][m] = (unsigned)v; Al[kp][m] = (unsigned)(v >> 32);
        }
#pragma unroll
        for (int p = 0; p < 8; p++) {
            int e = tid + p * 256;
            int kp = e >> 7, jf = e & 127;
            unsigned long long v =
                g_kgs[((size_t)t * (C_ / 2) + kp0 + kp) * HD_ + m0 + jf];
            Bh[kp][jf] = (unsigned)v; Bl[kp][jf] = (unsigned)(v >> 32);
        }
        __syncthreads();
#pragma unroll
        for (int ks = 0; ks < 2; ks++) {
            int kb = ks * 8;
            unsigned bh[4][2], bl[4][2];
#pragma unroll
            for (int j = 0; j < 4; j++) {
                int col = wn + j * 8 + lq;
                bh[j][0] = Bh[kb + lr][col];     bh[j][1] = Bh[kb + lr + 4][col];
                bl[j][0] = Bl[kb + lr][col];     bl[j][1] = Bl[kb + lr + 4][col];
            }
#pragma unroll
            for (int i = 0; i < 4; i++) {
                int m = wm + i * 16 + lq;
                unsigned ah0 = Ah[kb + lr][m],     ah1 = Ah[kb + lr][m + 8];
                unsigned ah2 = Ah[kb + lr + 4][m], ah3 = Ah[kb + lr + 4][m + 8];
                unsigned al0 = Al[kb + lr][m],     al1 = Al[kb + lr][m + 8];
                unsigned al2 = Al[kb + lr + 4][m], al3 = Al[kb + lr + 4][m + 8];
#pragma unroll
                for (int j = 0; j < 4; j++) {
                    mma16816(acc[i][j], ah0, ah1, ah2, ah3, bh[j][0], bh[j][1]);
                    mma16816(acc[i][j], ah0, ah1, ah2, ah3, bl[j][0], bl[j][1]);
                    mma16816(acc[i][j], al0, al1, al2, al3, bh[j][0], bh[j][1]);
                }
            }
        }
        __syncthreads();
    }
    // epilogue: store v (+bg) and per-head Ws partial dots
    float* outb = g_v + (size_t)bt * (N_ * HD_);
    int hloc = wn >> 6;
    int band = (wn >> 5) & 1;
#pragma unroll
    for (int i = 0; i < 4; i++) {
        int row = n0 + wm + i * 16 + lq;
        float p0 = 0.f, p1 = 0.f;
#pragma unroll
        for (int j = 0; j < 4; j++) {
            int col = m0 + wn + j * 8 + lr * 2;
            float2 bgv = *(const float2*)(bg + t * HD_ + col);
            float ws0 = Ws[col], ws1 = Ws[col + 1];
            float o00 = acc[i][j][0] + bgv.x, o01 = acc[i][j][1] + bgv.y;
            float o10 = acc[i][j][2] + bgv.x, o11 = acc[i][j][3] + bgv.y;
            *(float2*)(outb + (size_t)row * HD_ + col) = make_float2(o00, o01);
            *(float2*)(outb + (size_t)(row + 8) * HD_ + col) = make_float2(o10, o11);
            p0 = fmaf(o00, ws0, fmaf(o01, ws1, p0));
            p1 = fmaf(o10, ws0, fmaf(o11, ws1, p1));
        }
        p0 += __shfl_xor_sync(0xffffffffu, p0, 1);
        p0 += __shfl_xor_sync(0xffffffffu, p0, 2);
        p1 += __shfl_xor_sync(0xffffffffu, p1, 1);
        p1 += __shfl_xor_sync(0xffffffffu, p1, 2);
        if (lr == 0) {
            svp[wm + i * 16 + lq][hloc][band] = p0;
            svp[wm + i * 16 + lq + 8][hloc][band] = p1;
        }
    }
    __syncthreads();
    {
        int r = tid >> 1, hl = tid & 1;
        g_sv[((size_t)bt * N_ + n0 + r) * H_ + (m0 >> 6) + hl] =
            svp[r][hl][0] + svp[r][hl][1];
    }
}

// ---------------- 5) fused time-mix + signal projection (tensor) ----------------
__global__ void __launch_bounds__(256) updsig_kernel(
    const float* __restrict__ Wf, const float* __restrict__ bf,
    const float* __restrict__ sig, float* __restrict__ out_sig) {
    __shared__ float Vt[12][16][20];
    __shared__ unsigned Ah[8][200], Al[8][200];
    __shared__ unsigned Bh[8][72], Bl[8][72];
    __shared__ float sws[H_][T_][T_];
    int n0 = blockIdx.x * 16;
    int b = blockIdx.y;
    int tid = threadIdx.x, lane = tid & 31, wid = tid >> 5;
    int wr = wid & 3, wc = wid >> 2;
    int lq = lane >> 2, lr = lane & 3;

    for (int i = tid; i < H_ * T_ * T_; i += 256)
        ((float*)sws)[i] = g_w[((i / 144) * B_ + b) * 144 + (i % 144)];

    float acc[3][4][4];
#pragma unroll
    for (int i = 0; i < 3; i++)
#pragma unroll
        for (int j = 0; j < 4; j++)
#pragma unroll
            for (int r = 0; r < 4; r++) acc[i][j][r] = 0.f;

    int qq = tid >> 4, ni = tid & 15;
    float wreg[T_];
    __syncthreads();

    for (int s = 0; s < 32; s++) {
        int k0 = s * 16;
#pragma unroll
        for (int p = 0; p < 3; p++) {
            int e = tid + p * 256;
            int r = e >> 2, f4 = e & 3;
            int t = r >> 4, nn = r & 15;
            float4 v = *(const float4*)(g_v +
                ((size_t)(b * T_ + t) * N_ + n0 + nn) * HD_ + k0 + f4 * 4);
            *(float4*)&Vt[t][nn][f4 * 4] = v;
        }
        __syncthreads();
        if (tid < 192) {
            if ((s & 3) == 0) {
                int h = s >> 2;
#pragma unroll
                for (int t = 0; t < T_; t++) wreg[t] = sws[h][qq][t];
            }
            float s0[8], s1[8];
#pragma unroll
            for (int kp = 0; kp < 8; kp++) { s0[kp] = 0.f; s1[kp] = 0.f; }
#pragma unroll
            for (int t = 0; t < T_; t++) {
                float wv = wreg[t];
#pragma unroll
                for (int kp = 0; kp < 8; kp++) {
                    float2 v = *(const float2*)&Vt[t][ni][kp * 2];
                    s0[kp] = fmaf(wv, v.x, s0[kp]);
                    s1[kp] = fmaf(wv, v.y, s1[kp]);
                }
            }
#pragma unroll
            for (int kp = 0; kp < 8; kp++) {
                unsigned h, l;
                split2(s0[kp], s1[kp], h, l);
                Ah[kp][qq * 16 + ni] = h;
                Al[kp][qq * 16 + ni] = l;
            }
        } else {
            int t64 = tid - 192;
#pragma unroll
            for (int p = 0; p < 8; p++) {
                int e = t64 + p * 64;
                int kpp = e >> 6, c = e & 63;
                unsigned h, l;
                split2(Wf[(size_t)(k0 + 2 * kpp) * C_ + c],
                       Wf[(size_t)(k0 + 2 * kpp + 1) * C_ + c], h, l);
                Bh[kpp][c] = h; Bl[kpp][c] = l;
            }
        }
        __syncthreads();
        {
            unsigned bh[4][2], bl[4][2];
#pragma unroll
            for (int j = 0; j < 4; j++) {
                int col = wc * 32 + j * 8 + lq;
                bh[j][0] = Bh[lr][col];     bh[j][1] = Bh[lr + 4][col];
                bl[j][0] = Bl[lr][col];     bl[j][1] = Bl[lr + 4][col];
            }
#pragma unroll
            for (int i = 0; i < 3; i++) {
                int m = wr * 48 + i * 16 + lq;
                unsigned ah0 = Ah[lr][m],     ah1 = Ah[lr][m + 8];
                unsigned ah2 = Ah[lr + 4][m], ah3 = Ah[lr + 4][m + 8];
                unsigned al0 = Al[lr][m],     al1 = Al[lr][m + 8];
                unsigned al2 = Al[lr + 4][m], al3 = Al[lr + 4][m + 8];
#pragma unroll
                for (int j = 0; j < 4; j++) {
                    mma16816(acc[i][j], ah0, ah1, ah2, ah3, bh[j][0], bh[j][1]);
                    mma16816(acc[i][j], ah0, ah1, ah2, ah3, bl[j][0], bl[j][1]);
                    mma16816(acc[i][j], al0, al1, al2, al3, bh[j][0], bh[j][1]);
                }
            }
        }
        __syncthreads();
    }
#pragma unroll
    for (int i = 0; i < 3; i++) {
        int q_ = wr * 3 + i;
        int nn = n0 + lq;
#pragma unroll
        for (int j = 0; j < 4; j++) {
            int c = wc * 32 + j * 8 + lr * 2;
            float bf0 = bf[c], bf1 = bf[c + 1];
            size_t o0 = ((size_t)(b * T_ + q_) * N_ + nn) * C_ + c;
            size_t o1 = ((size_t)(b * T_ + q_) * N_ + nn + 8) * C_ + c;
            float2 sg0 = *(const float2*)(sig + o0);
            float2 sg1 = *(const float2*)(sig + o1);
            *(float2*)(out_sig + o0) =
                make_float2(fmaxf(acc[i][j][0] + bf0, 0.f) + sg0.x,
                            fmaxf(acc[i][j][1] + bf1, 0.f) + sg0.y);
            *(float2*)(out_sig + o1) =
                make_float2(fmaxf(acc[i][j][2] + bf0, 0.f) + sg1.x,
                            fmaxf(acc[i][j][3] + bf1, 0.f) + sg1.y);
        }
    }
}

// ---------------- 6) state mix ----------------
__global__ void statemix_kernel(const float* __restrict__ state,
                                const float* __restrict__ bs,
                                float* __restrict__ out_state) {
    __shared__ float sws[H_][T_][T_];
    int b = blockIdx.y;
    int n = blockIdx.x * 128 + threadIdx.x;
    for (int i = threadIdx.x; i < H_ * T_ * T_; i += 128)
        ((float*)sws)[i] = g_w[((i / 144) * B_ + b) * 144 + (i % 144)];
    __syncthreads();
    float st[T_];
#pragma unroll
    for (int q = 0; q < T_; q++) st[q] = 0.f;
#pragma unroll
    for (int t = 0; t < T_; t++) {
        const float* svp = g_sv + ((size_t)(b * T_ + t) * N_ + n) * H_;
        float4 a = *(const float4*)svp;
        float4 c = *(const float4*)(svp + 4);
        float hv[8] = {a.x, a.y, a.z, a.w, c.x, c.y, c.z, c.w};
#pragma unroll
        for (int q = 0; q < T_; q++) {
            float s = 0.f;
#pragma unroll
            for (int h = 0; h < H_; h++) s = fmaf(sws[h][q][t], hv[h], s);
            st[q] += s;
        }
    }
#pragma unroll
    for (int q = 0; q < T_; q++) {
        size_t idx = (size_t)(b * T_ + q) * N_ + n;
        out_state[idx] = state[idx] + fmaxf(st[q] + bs[0], 0.f);
    }
}

// ---------------- LayerNorm statistics ----------------
__global__ void red_state_kernel(const float* __restrict__ ys) {
    __shared__ double ss[256], sq[256];
    int b = blockIdx.x;
    int tid = threadIdx.x;
    double s = 0, q = 0;
    for (int i = tid; i < T_ * N_; i += 256) {
        double x = ys[b * T_ * N_ + i];
        s += x; q += x * x;
    }
    ss[tid] = s; sq[tid] = q;
    __syncthreads();
    for (int o = 128; o; o >>= 1) {
        if (tid < o) { ss[tid] += ss[tid + o]; sq[tid] += sq[tid + o]; }
        __syncthreads();
    }
    if (tid == 0) {
        double cnt = (double)(T_ * N_);
        double mean = ss[0] / cnt;
        double var = sq[0] / cnt - mean * mean;
        g_stats[b * 4 + 0] = (float)mean;
        g_stats[b * 4 + 1] = rsqrtf((float)var + EPSV);
    }
}

__global__ void red_sig1_kernel(const float* __restrict__ yg) {
    __shared__ double ss[256], sq[256];
    int b = blockIdx.y, blk = blockIdx.x;
    int tid = threadIdx.x;
    const float* base = yg + (size_t)b * (T_ * N_ * C_) + blk * 8192;
    double s = 0, q = 0;
    for (int i = tid; i < 8192; i += 256) {
        double x = base[i];
        s += x; q += x * x;
    }
    ss[tid] = s; sq[tid] = q;
    __syncthreads();
    for (int o = 128; o; o >>= 1) {
        if (tid < o) { ss[tid] += ss[tid + o]; sq[tid] += sq[tid + o]; }
        __syncthreads();
    }
    if (tid == 0) {
        g_part[(b * 96 + blk) * 2 + 0] = ss[0];
        g_part[(b * 96 + blk) * 2 + 1] = sq[0];
    }
}

__global__ void red_sig2_kernel() {
    __shared__ double ss[128], sq[128];
    int b = blockIdx.x;
    int tid = threadIdx.x;
    double s = 0, q = 0;
    if (tid < 96) {
        s = g_part[(b * 96 + tid) * 2 + 0];
        q = g_part[(b * 96 + tid) * 2 + 1];
    }
    ss[tid] = s; sq[tid] = q;
    __syncthreads();
    for (int o = 64; o; o >>= 1) {
        if (tid < o) { ss[tid] += ss[tid + o]; sq[tid] += sq[tid + o]; }
        __syncthreads();
    }
    if (tid == 0) {
        double cnt = (double)T_ * N_ * C_;
        double mean = ss[0] / cnt;
        double var = sq[0] / cnt - mean * mean;
        g_stats[b * 4 + 2] = (float)mean;
        g_stats[b * 4 + 3] = rsqrtf((float)var + EPSV);
    }
}

// ---------------- in-place normalization ----------------
__global__ void norm_state_kernel(float* __restrict__ ys,
                                  const float* __restrict__ gamma,
                                  const float* __restrict__ beta) {
    int idx = blockIdx.x * 256 + threadIdx.x;
    int b = idx / (T_ * N_);
    int r = idx % (T_ * N_);
    float m = g_stats[b * 4 + 0];
    float rs = g_stats[b * 4 + 1];
    ys[idx] = (ys[idx] - m) * rs * gamma[r] + beta[r];
}

__global__ void norm_sig_kernel(float* __restrict__ yg,
                                const float* __restrict__ gamma,
                                const float* __restrict__ beta) {
    int idx = blockIdx.x * 256 + threadIdx.x;
    int b = idx / (T_ * N_ * C_);
    int r = idx % (T_ * N_ * C_);
    float m = g_stats[b * 4 + 2];
    float rs = g_stats[b * 4 + 3];
    yg[idx] = (yg[idx] - m) * rs * gamma[r] + beta[r];
}

// ---------------- launch ----------------
extern "C" void kernel_launch(void* const* d_in, const int* in_sizes, int n_in,
                              void* d_out, int out_size) {
    const float* graph_state  = (const float*)d_in[0];
    const float* graph_signal = (const float*)d_in[1];
    const float* adj          = (const float*)d_in[2];
    const float* Wq           = (const float*)d_in[3];
    const float* bq           = (const float*)d_in[4];
    const float* Wk           = (const float*)d_in[5];
    const float* bk           = (const float*)d_in[6];
    const float* Kg           = (const float*)d_in[7];
    const float* bg           = (const float*)d_in[8];
    const float* Ws           = (const float*)d_in[9];
    const float* bs           = (const float*)d_in[10];
    const float* Wf           = (const float*)d_in[11];
    const float* bf           = (const float*)d_in[12];
    const float* gs_gamma     = (const float*)d_in[13];
    const float* gs_beta      = (const float*)d_in[14];
    const float* sg_gamma     = (const float*)d_in[15];
    const float* sg_beta      = (const float*)d_in[16];

    float* out_state  = (float*)d_out;
    float* out_signal = out_state + BT_ * N_;

    presplit_adj_kernel<<<(N_ * N_ / 2) / 256, 256>>>(adj);
    presplit_sig_kernel<<<(BT_ * (N_ / 2) * C_) / 256, 256>>>(graph_signal);
    presplit_kg_kernel<<<(T_ * (C_ / 2) * HD_) / 256, 256>>>(Kg);
    qk_kernel<<<BT_, HD_>>>(graph_state, Wq, bq, Wk, bk);
    attw_kernel<<<H_ * B_, 160>>>();
    aggT_kernel<<<dim3(48, 8), 256>>>();
    vT_kernel<<<dim3(HD_ / 128, N_ / 128, BT_), 256>>>(bg, Ws);
    updsig_kernel<<<dim3(64, 8), 256>>>(Wf, bf, graph_signal, out_signal);
    statemix_kernel<<<dim3(8, 8), 128>>>(graph_state, bs, out_state);
    red_state_kernel<<<B_, 256>>>(out_state);
    red_sig1_kernel<<<dim3(96, B_), 256>>>(out_signal);
    red_sig2_kernel<<<B_, 128>>>();
    norm_state_kernel<<<(BT_ * N_) / 256, 256>>>(out_state, gs_gamma, gs_beta);
    norm_sig_kernel<<<(BT_ * N_ * C_) / 256, 256>>>(out_signal, sg_gamma, sg_beta);
}

// round 8
// speedup vs baseline: 1.6501x; 1.0842x over previous
#include <cuda_runtime.h>
#include <cuda_bf16.h>

#define B_ 8
#define T_ 12
#define N_ 1024
#define C_ 64
#define H_ 8
#define D_ 64
#define HD_ 512
#define BT_ 96
#define EPSV 1e-3f

// ---------------- bf16 split + mma helpers ----------------
__device__ __forceinline__ void split2(float x0, float x1, unsigned& hi, unsigned& lo) {
    __nv_bfloat16 h0 = __float2bfloat16(x0);
    __nv_bfloat16 h1 = __float2bfloat16(x1);
    __nv_bfloat16 l0 = __float2bfloat16(x0 - __bfloat162float(h0));
    __nv_bfloat16 l1 = __float2bfloat16(x1 - __bfloat162float(h1));
    hi = ((unsigned)__bfloat16_as_ushort(h1) << 16) | (unsigned)__bfloat16_as_ushort(h0);
    lo = ((unsigned)__bfloat16_as_ushort(l1) << 16) | (unsigned)__bfloat16_as_ushort(l0);
}
__device__ __forceinline__ unsigned long long splitpack(float x0, float x1) {
    unsigned h, l;
    split2(x0, x1, h, l);
    return (unsigned long long)h | ((unsigned long long)l << 32);
}

__device__ __forceinline__ void mma16816(float* c, unsigned a0, unsigned a1,
                                         unsigned a2, unsigned a3,
                                         unsigned b0, unsigned b1) {
    asm volatile(
        "mma.sync.aligned.m16n8k16.row.col.f32.bf16.bf16.f32 "
        "{%0,%1,%2,%3},{%4,%5,%6,%7},{%8,%9},{%0,%1,%2,%3};"
        : "+f"(c[0]), "+f"(c[1]), "+f"(c[2]), "+f"(c[3])
        : "r"(a0), "r"(a1), "r"(a2), "r"(a3), "r"(b0), "r"(b1));
}

// ---------------- scratch ----------------
__device__ float g_q[BT_ * HD_];
__device__ float g_k[BT_ * HD_];
__device__ float g_w[H_ * B_ * T_ * T_];
__device__ unsigned long long g_adjs[N_ * (N_ / 2)];               // 4 MB
__device__ unsigned long long g_sigs[BT_ * (N_ / 2) * C_];         // 25 MB
__device__ unsigned long long g_kgs[T_ * (C_ / 2) * HD_];          // 1.5 MB
__device__ unsigned long long g_aggs[(size_t)BT_ * N_ * (C_ / 2)]; // 25 MB
__device__ unsigned long long g_states[(N_ / 2) * BT_];            // 0.4 MB split state [kp][bt]
__device__ unsigned long long g_wqs[(N_ / 2) * HD_];               // 2 MB split Wq [kp][hd]
__device__ unsigned long long g_wks[(N_ / 2) * HD_];               // 2 MB split Wk [kp][hd]
__device__ float g_v[(size_t)B_ * T_ * N_ * HD_];                  // 201 MB
__device__ float g_sv[BT_ * N_ * H_];                              // 3 MB
__device__ double g_part[B_ * 96 * 2];
__device__ float g_stats[B_ * 4];

// ---------------- 0) pre-split kernels ----------------
__global__ void presplit_adj_kernel(const float* __restrict__ adj) {
    int idx = blockIdx.x * 256 + threadIdx.x;
    int n = idx >> 9, kp = idx & 511;
    float2 v = *(const float2*)(adj + (size_t)n * N_ + 2 * kp);
    g_adjs[idx] = splitpack(v.x, v.y);
}
__global__ void presplit_sig_kernel(const float* __restrict__ sig) {
    int idx = blockIdx.x * 256 + threadIdx.x;
    int bt = idx / ((N_ / 2) * C_);
    int r = idx % ((N_ / 2) * C_);
    int kp = r / C_, c = r % C_;
    const float* s = sig + ((size_t)bt * N_ + 2 * kp) * C_ + c;
    g_sigs[idx] = splitpack(s[0], s[C_]);
}
__global__ void presplit_kg_kernel(const float* __restrict__ Kg) {
    int idx = blockIdx.x * 256 + threadIdx.x;
    int t = idx / ((C_ / 2) * HD_);
    int r = idx % ((C_ / 2) * HD_);
    int kp = r / HD_, m = r % HD_;
    const float* s = Kg + ((size_t)t * C_ + 2 * kp) * HD_ + m;
    g_kgs[idx] = splitpack(s[0], s[HD_]);
}
__global__ void presplit_w_kernel(const float* __restrict__ Wq,
                                  const float* __restrict__ Wk) {
    int idx = blockIdx.x * 256 + threadIdx.x;        // (N/2)*HD = 262144
    int kp = idx / HD_, m = idx % HD_;
    const float* W = blockIdx.y ? Wk : Wq;
    unsigned long long* o = blockIdx.y ? g_wks : g_wqs;
    o[idx] = splitpack(W[(size_t)(2 * kp) * HD_ + m], W[(size_t)(2 * kp + 1) * HD_ + m]);
}
__global__ void presplit_state_kernel(const float* __restrict__ state) {
    int idx = blockIdx.x * 256 + threadIdx.x;        // (N/2)*BT = 49152
    int kp = idx / BT_, bt = idx % BT_;
    g_states[idx] = splitpack(state[(size_t)bt * N_ + 2 * kp],
                              state[(size_t)bt * N_ + 2 * kp + 1]);
}

// ---------------- 1) q/k projections (tensor) ----------------
// [96,1024] @ [1024,512] for Wq (y=0) and Wk (y=1). Col tile 64, 8 warps x 8 cols.
__global__ void __launch_bounds__(256) qkT_kernel(const float* __restrict__ bq,
                                                  const float* __restrict__ bk) {
    __shared__ unsigned Ah[16][104], Al[16][104], Bh[16][72], Bl[16][72];
    int j0 = blockIdx.x * 64;
    int isk = blockIdx.y;
    const unsigned long long* W = isk ? g_wks : g_wqs;
    int tid = threadIdx.x, lane = tid & 31, wc = tid >> 5;
    int lq = lane >> 2, lr = lane & 3;

    float acc[6][4];
#pragma unroll
    for (int i = 0; i < 6; i++)
#pragma unroll
        for (int r = 0; r < 4; r++) acc[i][r] = 0.f;

    for (int kc = 0; kc < 32; kc++) {
        int kp0 = kc * 16;
#pragma unroll
        for (int p = 0; p < 6; p++) {
            int e = tid + p * 256;    // 1536 slots = 16 kp x 96 m
            int kp = e & 15, m = e >> 4;
            unsigned long long v = g_states[(size_t)(kp0 + kp) * BT_ + m];
            Ah[kp][m] = (unsigned)v; Al[kp][m] = (unsigned)(v >> 32);
        }
#pragma unroll
        for (int p = 0; p < 4; p++) {
            int e = tid + p * 256;    // 1024 slots = 16 kp x 64 col
            int kp = e >> 6, jf = e & 63;
            unsigned long long v = W[(size_t)(kp0 + kp) * HD_ + j0 + jf];
            Bh[kp][jf] = (unsigned)v; Bl[kp][jf] = (unsigned)(v >> 32);
        }
        __syncthreads();
#pragma unroll
        for (int ks = 0; ks < 2; ks++) {
            int kb = ks * 8;
            int col = wc * 8 + lq;
            unsigned bh0 = Bh[kb + lr][col], bh1 = Bh[kb + lr + 4][col];
            unsigned bl0 = Bl[kb + lr][col], bl1 = Bl[kb + lr + 4][col];
#pragma unroll
            for (int i = 0; i < 6; i++) {
                int m = i * 16 + lq;
                unsigned ah0 = Ah[kb + lr][m],     ah1 = Ah[kb + lr][m + 8];
                unsigned ah2 = Ah[kb + lr + 4][m], ah3 = Ah[kb + lr + 4][m + 8];
                unsigned al0 = Al[kb + lr][m],     al1 = Al[kb + lr][m + 8];
                unsigned al2 = Al[kb + lr + 4][m], al3 = Al[kb + lr + 4][m + 8];
                mma16816(acc[i], ah0, ah1, ah2, ah3, bh0, bh1);
                mma16816(acc[i], ah0, ah1, ah2, ah3, bl0, bl1);
                mma16816(acc[i], al0, al1, al2, al3, bh0, bh1);
            }
        }
        __syncthreads();
    }
    const float* bias = isk ? bk : bq;
    float* out = isk ? g_k : g_q;
    int col = j0 + wc * 8 + lr * 2;
    float b0 = bias[col], b1 = bias[col + 1];
#pragma unroll
    for (int i = 0; i < 6; i++) {
        int row = i * 16 + lq;
        *(float2*)(out + (size_t)row * HD_ + col) =
            make_float2(acc[i][0] + b0, acc[i][1] + b1);
        *(float2*)(out + (size_t)(row + 8) * HD_ + col) =
            make_float2(acc[i][2] + b0, acc[i][3] + b1);
    }
}

// ---------------- 2) attention weights ----------------
__global__ void attw_kernel() {
    __shared__ float sc[T_][T_];
    int b = blockIdx.x % B_;
    int h = blockIdx.x / B_;
    int t = threadIdx.x;
    int i = t / T_, j = t % T_;
    if (t < T_ * T_) {
        const float* qp = &g_q[(b * T_ + i) * HD_ + h * D_];
        const float* kp = &g_k[(b * T_ + j) * HD_ + h * D_];
        float d = 0.f;
#pragma unroll
        for (int x = 0; x < D_; x++) d = fmaf(qp[x], kp[x], d);
        sc[i][j] = d * 0.125f;
    }
    __syncthreads();
    if (t < T_ * T_) {
        float mx = -1e30f;
#pragma unroll
        for (int x = 0; x < T_; x++) mx = fmaxf(mx, sc[i][x]);
        float sm = 0.f;
#pragma unroll
        for (int x = 0; x < T_; x++) sm += expf(sc[i][x] - mx);
        g_w[((h * B_ + b) * T_ + i) * T_ + j] = expf(sc[i][j] - mx) / sm;
    }
}

// ---------------- 3) agg = adj @ sig_cat (tensor, pre-split) ----------------
__global__ void __launch_bounds__(256, 2) aggT_kernel() {
    __shared__ unsigned Ah[16][136], Al[16][136], Bh[16][136], Bl[16][136];
    int j0 = blockIdx.x * 128;
    int n0 = blockIdx.y * 128;
    int tid = threadIdx.x, lane = tid & 31, wid = tid >> 5;
    int wm = (wid & 1) * 64, wn = (wid >> 1) * 32;
    int lq = lane >> 2, lr = lane & 3;

    float acc[4][4][4];
#pragma unroll
    for (int i = 0; i < 4; i++)
#pragma unroll
        for (int j = 0; j < 4; j++)
#pragma unroll
            for (int r = 0; r < 4; r++) acc[i][j][r] = 0.f;

    for (int k0 = 0; k0 < N_; k0 += 32) {
        int kp0 = k0 >> 1;
#pragma unroll
        for (int p = 0; p < 8; p++) {
            int e = tid + p * 256;
            int kp = e & 15, m = e >> 4;
            unsigned long long v = g_adjs[(size_t)(n0 + m) * (N_ / 2) + kp0 + kp];
            Ah[kp][m] = (unsigned)v; Al[kp][m] = (unsigned)(v >> 32);
        }
#pragma unroll
        for (int p = 0; p < 8; p++) {
            int e = tid + p * 256;
            int kp = e >> 7, jf = e & 127;
            int j = j0 + jf, bt = j >> 6, c = j & 63;
            unsigned long long v =
                g_sigs[((size_t)bt * (N_ / 2) + kp0 + kp) * C_ + c];
            Bh[kp][jf] = (unsigned)v; Bl[kp][jf] = (unsigned)(v >> 32);
        }
        __syncthreads();
#pragma unroll
        for (int ks = 0; ks < 2; ks++) {
            int kb = ks * 8;
            unsigned bh[4][2], bl[4][2];
#pragma unroll
            for (int j = 0; j < 4; j++) {
                int col = wn + j * 8 + lq;
                bh[j][0] = Bh[kb + lr][col];     bh[j][1] = Bh[kb + lr + 4][col];
                bl[j][0] = Bl[kb + lr][col];     bl[j][1] = Bl[kb + lr + 4][col];
            }
#pragma unroll
            for (int i = 0; i < 4; i++) {
                int m = wm + i * 16 + lq;
                unsigned ah0 = Ah[kb + lr][m],     ah1 = Ah[kb + lr][m + 8];
                unsigned ah2 = Ah[kb + lr + 4][m], ah3 = Ah[kb + lr + 4][m + 8];
                unsigned al0 = Al[kb + lr][m],     al1 = Al[kb + lr][m + 8];
                unsigned al2 = Al[kb + lr + 4][m], al3 = Al[kb + lr + 4][m + 8];
#pragma unroll
                for (int j = 0; j < 4; j++) {
                    mma16816(acc[i][j], ah0, ah1, ah2, ah3, bh[j][0], bh[j][1]);
                    mma16816(acc[i][j], ah0, ah1, ah2, ah3, bl[j][0], bl[j][1]);
                    mma16816(acc[i][j], al0, al1, al2, al3, bh[j][0], bh[j][1]);
                }
            }
        }
        __syncthreads();
    }
#pragma unroll
    for (int i = 0; i < 4; i++) {
        int row = n0 + wm + i * 16 + lq;
#pragma unroll
        for (int j = 0; j < 4; j++) {
            int jcol = j0 + wn + j * 8 + lr * 2;
            int bt = jcol >> 6, c2 = (jcol & 63) >> 1;
            unsigned long long* o = g_aggs + ((size_t)bt * N_) * (C_ / 2) + c2;
            o[(size_t)row * (C_ / 2)] = splitpack(acc[i][j][0], acc[i][j][1]);
            o[(size_t)(row + 8) * (C_ / 2)] = splitpack(acc[i][j][2], acc[i][j][3]);
        }
    }
}

// ---------------- 4) v = agg @ Kg + bg (tensor) + Ws partial dots ----------------
__global__ void __launch_bounds__(256, 2) vT_kernel(const float* __restrict__ bg,
                                                    const float* __restrict__ Ws) {
    __shared__ unsigned Ah[16][136], Al[16][136], Bh[16][136], Bl[16][136];
    __shared__ float svp[128][2][2];
    int m0 = blockIdx.x * 128;
    int n0 = blockIdx.y * 128;
    int bt = blockIdx.z;
    int t = bt % T_;
    int tid = threadIdx.x, lane = tid & 31, wid = tid >> 5;
    int wm = (wid & 1) * 64, wn = (wid >> 1) * 32;
    int lq = lane >> 2, lr = lane & 3;

    float acc[4][4][4];
#pragma unroll
    for (int i = 0; i < 4; i++)
#pragma unroll
        for (int j = 0; j < 4; j++)
#pragma unroll
            for (int r = 0; r < 4; r++) acc[i][j][r] = 0.f;

    for (int k0 = 0; k0 < C_; k0 += 32) {
        int kp0 = k0 >> 1;
#pragma unroll
        for (int p = 0; p < 8; p++) {
            int e = tid + p * 256;
            int kp = e & 15, m = e >> 4;
            unsigned long long v =
                g_aggs[((size_t)bt * N_ + n0 + m) * (C_ / 2) + kp0 + kp];
            Ah[kp][m] = (unsigned)v; Al[kp][m] = (unsigned)(v >> 32);
        }
#pragma unroll
        for (int p = 0; p < 8; p++) {
            int e = tid + p * 256;
            int kp = e >> 7, jf = e & 127;
            unsigned long long v =
                g_kgs[((size_t)t * (C_ / 2) + kp0 + kp) * HD_ + m0 + jf];
            Bh[kp][jf] = (unsigned)v; Bl[kp][jf] = (unsigned)(v >> 32);
        }
        __syncthreads();
#pragma unroll
        for (int ks = 0; ks < 2; ks++) {
            int kb = ks * 8;
            unsigned bh[4][2], bl[4][2];
#pragma unroll
            for (int j = 0; j < 4; j++) {
                int col = wn + j * 8 + lq;
                bh[j][0] = Bh[kb + lr][col];     bh[j][1] = Bh[kb + lr + 4][col];
                bl[j][0] = Bl[kb + lr][col];     bl[j][1] = Bl[kb + lr + 4][col];
            }
#pragma unroll
            for (int i = 0; i < 4; i++) {
                int m = wm + i * 16 + lq;
                unsigned ah0 = Ah[kb + lr][m],     ah1 = Ah[kb + lr][m + 8];
                unsigned ah2 = Ah[kb + lr + 4][m], ah3 = Ah[kb + lr + 4][m + 8];
                unsigned al0 = Al[kb + lr][m],     al1 = Al[kb + lr][m + 8];
                unsigned al2 = Al[kb + lr + 4][m], al3 = Al[kb + lr + 4][m + 8];
#pragma unroll
                for (int j = 0; j < 4; j++) {
                    mma16816(acc[i][j], ah0, ah1, ah2, ah3, bh[j][0], bh[j][1]);
                    mma16816(acc[i][j], ah0, ah1, ah2, ah3, bl[j][0], bl[j][1]);
                    mma16816(acc[i][j], al0, al1, al2, al3, bh[j][0], bh[j][1]);
                }
            }
        }
        __syncthreads();
    }
    float* outb = g_v + (size_t)bt * (N_ * HD_);
    int hloc = wn >> 6;
    int band = (wn >> 5) & 1;
#pragma unroll
    for (int i = 0; i < 4; i++) {
        int row = n0 + wm + i * 16 + lq;
        float p0 = 0.f, p1 = 0.f;
#pragma unroll
        for (int j = 0; j < 4; j++) {
            int col = m0 + wn + j * 8 + lr * 2;
            float2 bgv = *(const float2*)(bg + t * HD_ + col);
            float ws0 = Ws[col], ws1 = Ws[col + 1];
            float o00 = acc[i][j][0] + bgv.x, o01 = acc[i][j][1] + bgv.y;
            float o10 = acc[i][j][2] + bgv.x, o11 = acc[i][j][3] + bgv.y;
            *(float2*)(outb + (size_t)row * HD_ + col) = make_float2(o00, o01);
            *(float2*)(outb + (size_t)(row + 8) * HD_ + col) = make_float2(o10, o11);
            p0 = fmaf(o00, ws0, fmaf(o01, ws1, p0));
            p1 = fmaf(o10, ws0, fmaf(o11, ws1, p1));
        }
        p0 += __shfl_xor_sync(0xffffffffu, p0, 1);
        p0 += __shfl_xor_sync(0xffffffffu, p0, 2);
        p1 += __shfl_xor_sync(0xffffffffu, p1, 1);
        p1 += __shfl_xor_sync(0xffffffffu, p1, 2);
        if (lr == 0) {
            svp[wm + i * 16 + lq][hloc][band] = p0;
            svp[wm + i * 16 + lq + 8][hloc][band] = p1;
        }
    }
    __syncthreads();
    {
        int r = tid >> 1, hl = tid & 1;
        g_sv[((size_t)bt * N_ + n0 + r) * H_ + (m0 >> 6) + hl] =
            svp[r][hl][0] + svp[r][hl][1];
    }
}

// ---------------- 5) fused time-mix + signal projection (tensor) ----------------
__global__ void __launch_bounds__(256) updsig_kernel(
    const float* __restrict__ Wf, const float* __restrict__ bf,
    const float* __restrict__ sig, float* __restrict__ out_sig) {
    __shared__ float Vt[12][16][20];
    __shared__ unsigned Ah[8][200], Al[8][200];
    __shared__ unsigned Bh[8][72], Bl[8][72];
    __shared__ float sws[H_][T_][T_];
    int n0 = blockIdx.x * 16;
    int b = blockIdx.y;
    int tid = threadIdx.x, lane = tid & 31, wid = tid >> 5;
    int wr = wid & 3, wc = wid >> 2;
    int lq = lane >> 2, lr = lane & 3;

    for (int i = tid; i < H_ * T_ * T_; i += 256)
        ((float*)sws)[i] = g_w[((i / 144) * B_ + b) * 144 + (i % 144)];

    float acc[3][4][4];
#pragma unroll
    for (int i = 0; i < 3; i++)
#pragma unroll
        for (int j = 0; j < 4; j++)
#pragma unroll
            for (int r = 0; r < 4; r++) acc[i][j][r] = 0.f;

    int qq = tid >> 4, ni = tid & 15;
    float wreg[T_];
    __syncthreads();

    for (int s = 0; s < 32; s++) {
        int k0 = s * 16;
#pragma unroll
        for (int p = 0; p < 3; p++) {
            int e = tid + p * 256;
            int r = e >> 2, f4 = e & 3;
            int t = r >> 4, nn = r & 15;
            float4 v = *(const float4*)(g_v +
                ((size_t)(b * T_ + t) * N_ + n0 + nn) * HD_ + k0 + f4 * 4);
            *(float4*)&Vt[t][nn][f4 * 4] = v;
        }
        __syncthreads();
        if (tid < 192) {
            if ((s & 3) == 0) {
                int h = s >> 2;
#pragma unroll
                for (int t = 0; t < T_; t++) wreg[t] = sws[h][qq][t];
            }
            float s0[8], s1[8];
#pragma unroll
            for (int kp = 0; kp < 8; kp++) { s0[kp] = 0.f; s1[kp] = 0.f; }
#pragma unroll
            for (int t = 0; t < T_; t++) {
                float wv = wreg[t];
#pragma unroll
                for (int kp = 0; kp < 8; kp++) {
                    float2 v = *(const float2*)&Vt[t][ni][kp * 2];
                    s0[kp] = fmaf(wv, v.x, s0[kp]);
                    s1[kp] = fmaf(wv, v.y, s1[kp]);
                }
            }
#pragma unroll
            for (int kp = 0; kp < 8; kp++) {
                unsigned h, l;
                split2(s0[kp], s1[kp], h, l);
                Ah[kp][qq * 16 + ni] = h;
                Al[kp][qq * 16 + ni] = l;
            }
        } else {
            int t64 = tid - 192;
#pragma unroll
            for (int p = 0; p < 8; p++) {
                int e = t64 + p * 64;
                int kpp = e >> 6, c = e & 63;
                unsigned h, l;
                split2(Wf[(size_t)(k0 + 2 * kpp) * C_ + c],
                       Wf[(size_t)(k0 + 2 * kpp + 1) * C_ + c], h, l);
                Bh[kpp][c] = h; Bl[kpp][c] = l;
            }
        }
        __syncthreads();
        {
            unsigned bh[4][2], bl[4][2];
#pragma unroll
            for (int j = 0; j < 4; j++) {
                int col = wc * 32 + j * 8 + lq;
                bh[j][0] = Bh[lr][col];     bh[j][1] = Bh[lr + 4][col];
                bl[j][0] = Bl[lr][col];     bl[j][1] = Bl[lr + 4][col];
            }
#pragma unroll
            for (int i = 0; i < 3; i++) {
                int m = wr * 48 + i * 16 + lq;
                unsigned ah0 = Ah[lr][m],     ah1 = Ah[lr][m + 8];
                unsigned ah2 = Ah[lr + 4][m], ah3 = Ah[lr + 4][m + 8];
                unsigned al0 = Al[lr][m],     al1 = Al[lr][m + 8];
                unsigned al2 = Al[lr + 4][m], al3 = Al[lr + 4][m + 8];
#pragma unroll
                for (int j = 0; j < 4; j++) {
                    mma16816(acc[i][j], ah0, ah1, ah2, ah3, bh[j][0], bh[j][1]);
                    mma16816(acc[i][j], ah0, ah1, ah2, ah3, bl[j][0], bl[j][1]);
                    mma16816(acc[i][j], al0, al1, al2, al3, bh[j][0], bh[j][1]);
                }
            }
        }
        __syncthreads();
    }
#pragma unroll
    for (int i = 0; i < 3; i++) {
        int q_ = wr * 3 + i;
        int nn = n0 + lq;
#pragma unroll
        for (int j = 0; j < 4; j++) {
            int c = wc * 32 + j * 8 + lr * 2;
            float bf0 = bf[c], bf1 = bf[c + 1];
            size_t o0 = ((size_t)(b * T_ + q_) * N_ + nn) * C_ + c;
            size_t o1 = ((size_t)(b * T_ + q_) * N_ + nn + 8) * C_ + c;
            float2 sg0 = *(const float2*)(sig + o0);
            float2 sg1 = *(const float2*)(sig + o1);
            *(float2*)(out_sig + o0) =
                make_float2(fmaxf(acc[i][j][0] + bf0, 0.f) + sg0.x,
                            fmaxf(acc[i][j][1] + bf1, 0.f) + sg0.y);
            *(float2*)(out_sig + o1) =
                make_float2(fmaxf(acc[i][j][2] + bf0, 0.f) + sg1.x,
                            fmaxf(acc[i][j][3] + bf1, 0.f) + sg1.y);
        }
    }
}

// ---------------- 6) state mix ----------------
__global__ void statemix_kernel(const float* __restrict__ state,
                                const float* __restrict__ bs,
                                float* __restrict__ out_state) {
    __shared__ float sws[H_][T_][T_];
    int b = blockIdx.y;
    int n = blockIdx.x * 128 + threadIdx.x;
    for (int i = threadIdx.x; i < H_ * T_ * T_; i += 128)
        ((float*)sws)[i] = g_w[((i / 144) * B_ + b) * 144 + (i % 144)];
    __syncthreads();
    float st[T_];
#pragma unroll
    for (int q = 0; q < T_; q++) st[q] = 0.f;
#pragma unroll
    for (int t = 0; t < T_; t++) {
        const float* svp = g_sv + ((size_t)(b * T_ + t) * N_ + n) * H_;
        float4 a = *(const float4*)svp;
        float4 c = *(const float4*)(svp + 4);
        float hv[8] = {a.x, a.y, a.z, a.w, c.x, c.y, c.z, c.w};
#pragma unroll
        for (int q = 0; q < T_; q++) {
            float s = 0.f;
#pragma unroll
            for (int h = 0; h < H_; h++) s = fmaf(sws[h][q][t], hv[h], s);
            st[q] += s;
        }
    }
#pragma unroll
    for (int q = 0; q < T_; q++) {
        size_t idx = (size_t)(b * T_ + q) * N_ + n;
        out_state[idx] = state[idx] + fmaxf(st[q] + bs[0], 0.f);
    }
}

// ---------------- LayerNorm statistics ----------------
__global__ void red_state_kernel(const float* __restrict__ ys) {
    __shared__ double ss[256], sq[256];
    int b = blockIdx.x;
    int tid = threadIdx.x;
    double s = 0, q = 0;
    for (int i = tid; i < T_ * N_; i += 256) {
        double x = ys[b * T_ * N_ + i];
        s += x; q += x * x;
    }
    ss[tid] = s; sq[tid] = q;
    __syncthreads();
    for (int o = 128; o; o >>= 1) {
        if (tid < o) { ss[tid] += ss[tid + o]; sq[tid] += sq[tid + o]; }
        __syncthreads();
    }
    if (tid == 0) {
        double cnt = (double)(T_ * N_);
        double mean = ss[0] / cnt;
        double var = sq[0] / cnt - mean * mean;
        g_stats[b * 4 + 0] = (float)mean;
        g_stats[b * 4 + 1] = rsqrtf((float)var + EPSV);
    }
}

__global__ void red_sig1_kernel(const float* __restrict__ yg) {
    __shared__ double ss[256], sq[256];
    int b = blockIdx.y, blk = blockIdx.x;
    int tid = threadIdx.x;
    const float* base = yg + (size_t)b * (T_ * N_ * C_) + blk * 8192;
    double s = 0, q = 0;
    for (int i = tid; i < 8192; i += 256) {
        double x = base[i];
        s += x; q += x * x;
    }
    ss[tid] = s; sq[tid] = q;
    __syncthreads();
    for (int o = 128; o; o >>= 1) {
        if (tid < o) { ss[tid] += ss[tid + o]; sq[tid] += sq[tid + o]; }
        __syncthreads();
    }
    if (tid == 0) {
        g_part[(b * 96 + blk) * 2 + 0] = ss[0];
        g_part[(b * 96 + blk) * 2 + 1] = sq[0];
    }
}

__global__ void red_sig2_kernel() {
    __shared__ double ss[128], sq[128];
    int b = blockIdx.x;
    int tid = threadIdx.x;
    double s = 0, q = 0;
    if (tid < 96) {
        s = g_part[(b * 96 + tid) * 2 + 0];
        q = g_part[(b * 96 + tid) * 2 + 1];
    }
    ss[tid] = s; sq[tid] = q;
    __syncthreads();
    for (int o = 64; o; o >>= 1) {
        if (tid < o) { ss[tid] += ss[tid + o]; sq[tid] += sq[tid + o]; }
        __syncthreads();
    }
    if (tid == 0) {
        double cnt = (double)T_ * N_ * C_;
        double mean = ss[0] / cnt;
        double var = sq[0] / cnt - mean * mean;
        g_stats[b * 4 + 2] = (float)mean;
        g_stats[b * 4 + 3] = rsqrtf((float)var + EPSV);
    }
}

// ---------------- in-place normalization ----------------
__global__ void norm_state_kernel(float* __restrict__ ys,
                                  const float* __restrict__ gamma,
                                  const float* __restrict__ beta) {
    int idx = blockIdx.x * 256 + threadIdx.x;
    int b = idx / (T_ * N_);
    int r = idx % (T_ * N_);
    float m = g_stats[b * 4 + 0];
    float rs = g_stats[b * 4 + 1];
    ys[idx] = (ys[idx] - m) * rs * gamma[r] + beta[r];
}

__global__ void norm_sig_kernel(float* __restrict__ yg,
                                const float* __restrict__ gamma,
                                const float* __restrict__ beta) {
    int idx = blockIdx.x * 256 + threadIdx.x;
    int b = idx / (T_ * N_ * C_);
    int r = idx % (T_ * N_ * C_);
    float m = g_stats[b * 4 + 2];
    float rs = g_stats[b * 4 + 3];
    yg[idx] = (yg[idx] - m) * rs * gamma[r] + beta[r];
}

// ---------------- launch ----------------
extern "C" void kernel_launch(void* const* d_in, const int* in_sizes, int n_in,
                              void* d_out, int out_size) {
    const float* graph_state  = (const float*)d_in[0];
    const float* graph_signal = (const float*)d_in[1];
    const float* adj          = (const float*)d_in[2];
    const float* Wq           = (const float*)d_in[3];
    const float* bq           = (const float*)d_in[4];
    const float* Wk           = (const float*)d_in[5];
    const float* bk           = (const float*)d_in[6];
    const float* Kg           = (const float*)d_in[7];
    const float* bg           = (const float*)d_in[8];
    const float* Ws           = (const float*)d_in[9];
    const float* bs           = (const float*)d_in[10];
    const float* Wf           = (const float*)d_in[11];
    const float* bf           = (const float*)d_in[12];
    const float* gs_gamma     = (const float*)d_in[13];
    const float* gs_beta      = (const float*)d_in[14];
    const float* sg_gamma     = (const float*)d_in[15];
    const float* sg_beta      = (const float*)d_in[16];

    float* out_state  = (float*)d_out;
    float* out_signal = out_state + BT_ * N_;

    presplit_adj_kernel<<<(N_ * N_ / 2) / 256, 256>>>(adj);
    presplit_sig_kernel<<<(BT_ * (N_ / 2) * C_) / 256, 256>>>(graph_signal);
    presplit_kg_kernel<<<(T_ * (C_ / 2) * HD_) / 256, 256>>>(Kg);
    presplit_w_kernel<<<dim3(((N_ / 2) * HD_) / 256, 2), 256>>>(Wq, Wk);
    presplit_state_kernel<<<((N_ / 2) * BT_) / 256, 256>>>(graph_state);
    qkT_kernel<<<dim3(8, 2), 256>>>(bq, bk);
    attw_kernel<<<H_ * B_, 160>>>();
    aggT_kernel<<<dim3(48, 8), 256>>>();
    vT_kernel<<<dim3(HD_ / 128, N_ / 128, BT_), 256>>>(bg, Ws);
    updsig_kernel<<<dim3(64, 8), 256>>>(Wf, bf, graph_signal, out_signal);
    statemix_kernel<<<dim3(8, 8), 128>>>(graph_state, bs, out_state);
    red_state_kernel<<<B_, 256>>>(out_state);
    red_sig1_kernel<<<dim3(96, B_), 256>>>(out_signal);
    red_sig2_kernel<<<B_, 128>>>();
    norm_state_kernel<<<(BT_ * N_) / 256, 256>>>(out_state, gs_gamma, gs_beta);
    norm_sig_kernel<<<(BT_ * N_ * C_) / 256, 256>>>(out_signal, sg_gamma, sg_beta);
}